// round 4
// baseline (speedup 1.0000x reference)
#include <cuda_runtime.h>
#include <math.h>
#include <stdint.h>

// ---------------------------------------------------------------------------
// OACNN block, fp32 SIMT pipeline. N=500000, C=64, K=27, 3 cluster scales.
// All float4-accessed device globals are force-aligned to 16B (nvlink gives
// plain float arrays only 4B alignment -> LDG.128 trap).
// ---------------------------------------------------------------------------

#define NPTS 500000
#define CDIM 64
#define KTAP 27
#define NCL0 4096
#define NCL1 32768
#define NCL2 131072
#define NCLS (NCL0 + NCL1 + NCL2)       // 167936
#define NT   ((NPTS + 127) / 128)       // 3907 tiles of 128 points
#define E4   (NPTS * 16)                // float4 elements over N*C

// ---- typed device globals, 16B-aligned ----
__device__ __align__(16) float d_S[(size_t)NCLS * CDIM];
__device__ __align__(16) float d_D[(size_t)NCLS * CDIM];
__device__ __align__(16) float d_G[(size_t)NCLS * CDIM];
__device__ __align__(16) float d_B1[(size_t)NPTS * CDIM];
__device__ __align__(16) float d_B2[(size_t)NPTS * CDIM];
__device__ __align__(16) float d_B3[(size_t)NPTS * CDIM];
__device__ __align__(16) float d_Mw[(size_t)NCL2 * CDIM];
__device__ __align__(16) float d_cntf[NCLS];
__device__ __align__(16) float d_gram[CDIM * CDIM];
__device__ __align__(16) float d_cs[CDIM];
__device__ __align__(16) float d_zstat[3 * 2 * CDIM];
__device__ __align__(16) float d_adp[(size_t)NPTS * 3];
__device__ __align__(16) float d_sb[7][2][CDIM];    // folded BN: lw0..2, proj0..3
__device__ __align__(16) float d_zsb[3][2][CDIM];   // BN: fuse, conv1, conv2
__device__ __align__(16) unsigned int d_gmaxu[4];   // global max keys (pad to 16B)

__device__ __forceinline__ int clpre(int sc) {
    return sc == 0 ? 0 : (sc == 1 ? NCL0 : (NCL0 + NCL1));
}

// monotone float->uint key (order-preserving map)
__device__ __forceinline__ unsigned int fkey(float v) {
    unsigned int b = __float_as_uint(v);
    return (b & 0x80000000u) ? ~b : (b ^ 0x80000000u);
}
__device__ __forceinline__ float funkey(unsigned int u) {
    unsigned int b = (u & 0x80000000u) ? (u ^ 0x80000000u) : ~u;
    return __uint_as_float(b);
}

// 128x64 @ 64x64 register-tiled GEMM body. Thread computes 4 rows x 8 cols.
__device__ __forceinline__ void gemm64(const float* __restrict__ Xs,
                                       const float* __restrict__ Ws,
                                       float acc[4][8], int r0, int c0) {
#pragma unroll
    for (int cc = 0; cc < 64; cc += 4) {
        float4 a4[4];
#pragma unroll
        for (int r = 0; r < 4; r++) a4[r] = *(const float4*)(Xs + (r0 + r) * 64 + cc);
#pragma unroll
        for (int u = 0; u < 4; u++) {
            float4 w0 = *(const float4*)(Ws + (cc + u) * 64 + c0);
            float4 w1 = *(const float4*)(Ws + (cc + u) * 64 + c0 + 4);
#pragma unroll
            for (int r = 0; r < 4; r++) {
                float a = (u == 0) ? a4[r].x : (u == 1) ? a4[r].y : (u == 2) ? a4[r].z : a4[r].w;
                acc[r][0] += a * w0.x; acc[r][1] += a * w0.y;
                acc[r][2] += a * w0.z; acc[r][3] += a * w0.w;
                acc[r][4] += a * w1.x; acc[r][5] += a * w1.y;
                acc[r][6] += a * w1.z; acc[r][7] += a * w1.w;
            }
        }
    }
}

// load 128x64 tile (rows base..base+127, guarded) into smem, stride 64
__device__ __forceinline__ void load_tile(float* Xs, const float* __restrict__ src,
                                          int base, int tid) {
    int r = tid >> 1, h = (tid & 1) * 32;
    bool v = (base + r) < NPTS;
    const float4* s = (const float4*)(src + (size_t)(base + r) * 64 + h);
    float4* d = (float4*)(Xs + r * 64 + h);
    float4 z = make_float4(0.f, 0.f, 0.f, 0.f);
#pragma unroll
    for (int i = 0; i < 8; i++) d[i] = v ? s[i] : z;
}

__device__ __forceinline__ void load_W(float* Ws, const float* __restrict__ src, int tid) {
    const float4* s = (const float4*)src;
    float4* d = (float4*)Ws;
#pragma unroll
    for (int i = 0; i < 4; i++) d[tid + i * 256] = s[tid + i * 256];
}

// epilogue BN-stat reduction without shared atomics.
// Each thread holds csum[8], csq[8] for cols c0..c0+7, row-group rg=tid>>3.
// scratch >= 4096 floats.
__device__ __forceinline__ void stat_reduce(float* scratch, const float csum[8],
                                            const float csq[8], int tid, int c0,
                                            int statq) {
    int rg = tid >> 3;  // 0..31
#pragma unroll
    for (int j = 0; j < 8; j++) {
        scratch[rg * 64 + c0 + j] = csum[j];
        scratch[2048 + rg * 64 + c0 + j] = csq[j];
    }
    __syncthreads();
    if (tid < 128) {
        int part = tid >> 6;      // 0 = sum, 1 = sumsq
        int c = tid & 63;
        const float* p = scratch + part * 2048 + c;
        float tot = 0.f;
#pragma unroll
        for (int rg2 = 0; rg2 < 32; rg2++) tot += p[rg2 * 64];
        atomicAdd(&d_zstat[statq * 128 + part * 64 + c], tot);
    }
}

// ---------------------------------------------------------------------------
__global__ __launch_bounds__(256) void k_zero() {
    long long i = (long long)blockIdx.x * 256 + threadIdx.x;
    long long stride = (long long)gridDim.x * 256;
    const long long nS = (long long)NCLS * CDIM;
    for (long long idx = i; idx < nS; idx += stride) {
        d_S[idx] = 0.f; d_D[idx] = 0.f; d_G[idx] = 0.f;
    }
    for (long long idx = i; idx < NCLS; idx += stride) d_cntf[idx] = 0.f;
    if (i < 4096) d_gram[i] = 0.f;
    if (i < 64) d_cs[i] = 0.f;
    if (i < 384) d_zstat[i] = 0.f;
    if (i < 3) d_gmaxu[i] = 0x007FFFFFu;   // key(-inf)
}

// Gram matrix + column sums + cluster counts + adp softmax
__global__ __launch_bounds__(256) void k_gram(const float* __restrict__ feat,
                                              const int* __restrict__ cl0,
                                              const int* __restrict__ cl1,
                                              const int* __restrict__ cl2,
                                              const float* __restrict__ W_adp) {
    __shared__ __align__(16) float Xs[128 * 64];
    __shared__ float Was[CDIM * 3];
    int tid = threadIdx.x;
    int base = blockIdx.x * 128;
    load_tile(Xs, feat, base, tid);
    if (tid < CDIM * 3) Was[tid] = W_adp[tid];
    __syncthreads();

    if (tid < 128 && base + tid < NPTS) {
        int n = base + tid;
        atomicAdd(&d_cntf[cl0[n]], 1.f);
        atomicAdd(&d_cntf[NCL0 + cl1[n]], 1.f);
        atomicAdd(&d_cntf[NCL0 + NCL1 + cl2[n]], 1.f);
        float a0 = 0.f, a1 = 0.f, a2 = 0.f;
#pragma unroll 8
        for (int c = 0; c < 64; c++) {
            float x = Xs[tid * 64 + c];
            a0 += x * Was[c * 3 + 0];
            a1 += x * Was[c * 3 + 1];
            a2 += x * Was[c * 3 + 2];
        }
        float mx = fmaxf(a0, fmaxf(a1, a2));
        float e0 = expf(a0 - mx), e1 = expf(a1 - mx), e2 = expf(a2 - mx);
        float inv = 1.f / (e0 + e1 + e2);
        d_adp[(size_t)n * 3 + 0] = e0 * inv;
        d_adp[(size_t)n * 3 + 1] = e1 * inv;
        d_adp[(size_t)n * 3 + 2] = e2 * inv;
    }

    // partial Gram: thread handles row i = tid&63, 16 cols at j0=(tid>>6)*16
    int i = tid & 63;
    int j0 = (tid >> 6) * 16;
    float acc[16];
#pragma unroll
    for (int q = 0; q < 16; q++) acc[q] = 0.f;
    for (int m = 0; m < 128; m++) {
        float a = Xs[m * 64 + i];
        const float4* xr = (const float4*)(Xs + m * 64 + j0);
#pragma unroll
        for (int q = 0; q < 4; q++) {
            float4 w = xr[q];
            acc[q * 4 + 0] += a * w.x; acc[q * 4 + 1] += a * w.y;
            acc[q * 4 + 2] += a * w.z; acc[q * 4 + 3] += a * w.w;
        }
    }
#pragma unroll
    for (int q = 0; q < 16; q++)
        atomicAdd(&d_gram[i * 64 + j0 + q], acc[q]);

    if (tid < 64) {
        float s = 0.f;
        for (int m = 0; m < 128; m++) s += Xs[m * 64 + tid];
        atomicAdd(&d_cs[tid], s);
    }
}

// fold BN of (feat @ W) into per-channel scale/bias via Gram trick
__global__ __launch_bounds__(512) void k_fold(const float* __restrict__ W_lw,
                                              const float* __restrict__ g_lw,
                                              const float* __restrict__ b_lw,
                                              const float* __restrict__ W_proj,
                                              const float* __restrict__ g_proj,
                                              const float* __restrict__ b_proj) {
    __shared__ __align__(16) float Gs[64 * 64];
    __shared__ float cs[64];
    int tid = threadIdx.x;
    for (int idx = tid; idx < 4096; idx += blockDim.x) Gs[idx] = d_gram[idx];
    if (tid < 64) cs[tid] = d_cs[tid];
    __syncthreads();
    if (tid < 448) {
        int q = tid >> 6, j = tid & 63;
        const float* W = q < 3 ? W_lw + q * 4096 : W_proj + (q - 3) * 4096;
        const float* g = q < 3 ? g_lw + q * 64 : g_proj + (q - 3) * 64;
        const float* b = q < 3 ? b_lw + q * 64 : b_proj + (q - 3) * 64;
        float wcol[64];
        for (int i = 0; i < 64; i++) wcol[i] = W[i * 64 + j];
        float mean = 0.f, m2 = 0.f;
        for (int i = 0; i < 64; i++) {
            mean += cs[i] * wcol[i];
            float t = 0.f;
            for (int i2 = 0; i2 < 64; i2++) t += Gs[i * 64 + i2] * wcol[i2];
            m2 += wcol[i] * t;
        }
        float invN = 1.f / (float)NPTS;
        mean *= invN; m2 *= invN;
        float var = m2 - mean * mean;
        float s = g[j] * rsqrtf(var + 1e-3f);
        d_sb[q][0][j] = s;
        d_sb[q][1][j] = b[j] - mean * s;
    }
}

// P = relu(bn(feat@W_lw)); write P(B1); segsum S[cl] += P
__global__ __launch_bounds__(256) void k_P(const float* __restrict__ feat,
                                           const float* __restrict__ W,
                                           const int* __restrict__ cl, int sc) {
    __shared__ __align__(16) float Xs[128 * 64];
    __shared__ __align__(16) float Ws[64 * 64];
    int tid = threadIdx.x, base = blockIdx.x * 128;
    load_tile(Xs, feat, base, tid);
    load_W(Ws, W, tid);
    __syncthreads();
    int r0 = (tid >> 3) * 4, c0 = (tid & 7) * 8;
    float acc[4][8] = {};
    gemm64(Xs, Ws, acc, r0, c0);
    float* S = d_S + (size_t)clpre(sc) * CDIM;
    float s[8], b[8];
#pragma unroll
    for (int j = 0; j < 8; j++) { s[j] = d_sb[sc][0][c0 + j]; b[j] = d_sb[sc][1][c0 + j]; }
#pragma unroll
    for (int r = 0; r < 4; r++) {
        int m = base + r0 + r;
        if (m < NPTS) {
            size_t cb = (size_t)cl[m] * 64;
#pragma unroll
            for (int j = 0; j < 8; j++) {
                float y = fmaxf(acc[r][j] * s[j] + b[j], 0.f);
                d_B1[(size_t)m * 64 + c0 + j] = y;
                atomicAdd(&S[cb + c0 + j], y);
            }
        }
    }
}

// Mw[c] = (S[c]/max(cnt,1)) @ W_w  over cluster rows
__global__ __launch_bounds__(256) void k_Mw(const float* __restrict__ Ww, int sc, int ncl) {
    __shared__ __align__(16) float Xs[128 * 64];
    __shared__ __align__(16) float Ws[64 * 64];
    int tid = threadIdx.x, base = blockIdx.x * 128;
    const float* S = d_S + (size_t)clpre(sc) * CDIM;
    const float* cnt = d_cntf + clpre(sc);
    {
        int r = tid >> 1, h = (tid & 1) * 32;
        int cr = base + r;
        bool v = cr < ncl;
        float inv = 0.f;
        if (v) inv = 1.f / fmaxf(cnt[cr], 1.f);
        const float4* s4 = (const float4*)(S + (size_t)cr * 64 + h);
        float4* dd = (float4*)(Xs + r * 64 + h);
        float4 z = make_float4(0.f, 0.f, 0.f, 0.f);
#pragma unroll
        for (int i = 0; i < 8; i++) {
            float4 x = v ? s4[i] : z;
            x.x *= inv; x.y *= inv; x.z *= inv; x.w *= inv;
            dd[i] = x;
        }
    }
    load_W(Ws, Ww, tid);
    __syncthreads();
    int r0 = (tid >> 3) * 4, c0 = (tid & 7) * 8;
    float acc[4][8] = {};
    gemm64(Xs, Ws, acc, r0, c0);
#pragma unroll
    for (int r = 0; r < 4; r++) {
        int m = base + r0 + r;
        if (m < ncl)
#pragma unroll
            for (int j = 0; j < 8; j++) d_Mw[(size_t)m * 64 + c0 + j] = acc[r][j];
    }
}

// T = P@W_w - Mw[cl]; write T(B2); global max -> d_gmaxu[sc]
__global__ __launch_bounds__(256) void k_T(const float* __restrict__ Ww,
                                           const int* __restrict__ cl, int sc) {
    __shared__ __align__(16) float Xs[128 * 64];
    __shared__ __align__(16) float Ws[64 * 64];
    int tid = threadIdx.x, base = blockIdx.x * 128;
    load_tile(Xs, d_B1, base, tid);
    load_W(Ws, Ww, tid);
    __syncthreads();
    int r0 = (tid >> 3) * 4, c0 = (tid & 7) * 8;
    float acc[4][8] = {};
    gemm64(Xs, Ws, acc, r0, c0);
    float lmax = -3.402823466e38f;
#pragma unroll
    for (int r = 0; r < 4; r++) {
        int m = base + r0 + r;
        if (m < NPTS) {
            size_t cb = (size_t)cl[m] * 64;
#pragma unroll
            for (int j = 0; j < 8; j++) {
                float t = acc[r][j] - d_Mw[cb + c0 + j];
                d_B2[(size_t)m * 64 + c0 + j] = t;
                lmax = fmaxf(lmax, t);
            }
        }
    }
#pragma unroll
    for (int off = 16; off > 0; off >>= 1)
        lmax = fmaxf(lmax, __shfl_xor_sync(0xFFFFFFFFu, lmax, off));
    if ((tid & 31) == 0) atomicMax(&d_gmaxu[sc], fkey(lmax));
}

// E = exp(T - max); D[cl] += E; in-place B2
__global__ __launch_bounds__(256) void k_E(const int* __restrict__ cl, int sc) {
    long long i = (long long)blockIdx.x * 256 + threadIdx.x;
    if (i >= E4) return;
    long long row = i >> 4;
    int c4 = (int)(i & 15) * 4;
    float M = funkey(d_gmaxu[sc]);
    float* D = d_D + (size_t)clpre(sc) * CDIM;
    float4 t = *(float4*)(d_B2 + row * 64 + c4);
    float4 e;
    e.x = expf(t.x - M); e.y = expf(t.y - M);
    e.z = expf(t.z - M); e.w = expf(t.w - M);
    *(float4*)(d_B2 + row * 64 + c4) = e;
    size_t cb = (size_t)cl[row] * 64 + c4;
    atomicAdd(&D[cb + 0], e.x); atomicAdd(&D[cb + 1], e.y);
    atomicAdd(&D[cb + 2], e.z); atomicAdd(&D[cb + 3], e.w);
}

// F = relu(bn(feat@W_proj)); G[cl] += F * E / (D[cl]+1e-6)
__global__ __launch_bounds__(256) void k_F(const float* __restrict__ feat,
                                           const float* __restrict__ Wp,
                                           const int* __restrict__ cl, int sc) {
    __shared__ __align__(16) float Xs[128 * 64];
    __shared__ __align__(16) float Ws[64 * 64];
    int tid = threadIdx.x, base = blockIdx.x * 128;
    load_tile(Xs, feat, base, tid);
    load_W(Ws, Wp, tid);
    __syncthreads();
    int r0 = (tid >> 3) * 4, c0 = (tid & 7) * 8;
    float acc[4][8] = {};
    gemm64(Xs, Ws, acc, r0, c0);
    int sb = 3 + sc;
    float* D = d_D + (size_t)clpre(sc) * CDIM;
    float* G = d_G + (size_t)clpre(sc) * CDIM;
    float s[8], b[8];
#pragma unroll
    for (int j = 0; j < 8; j++) { s[j] = d_sb[sb][0][c0 + j]; b[j] = d_sb[sb][1][c0 + j]; }
#pragma unroll
    for (int r = 0; r < 4; r++) {
        int m = base + r0 + r;
        if (m < NPTS) {
            size_t cb = (size_t)cl[m] * 64;
#pragma unroll
            for (int j = 0; j < 8; j++) {
                float F = fmaxf(acc[r][j] * s[j] + b[j], 0.f);
                float e = d_B2[(size_t)m * 64 + c0 + j];
                float dn = D[cb + c0 + j] + 1e-6f;
                atomicAdd(&G[cb + c0 + j], F * e / dn);
            }
        }
    }
}

// f_last, mix, z = [f_last,mix]@W_fuse; write z(B1); stats for fuse BN
__global__ __launch_bounds__(256) void k_fuse(const float* __restrict__ feat,
                                              const float* __restrict__ W_proj,
                                              const float* __restrict__ W_fuse,
                                              const int* __restrict__ cl0,
                                              const int* __restrict__ cl1,
                                              const int* __restrict__ cl2) {
    __shared__ __align__(16) float Xs[128 * 64];
    __shared__ __align__(16) float Ws[64 * 64];
    int tid = threadIdx.x, base = blockIdx.x * 128;
    int r0 = (tid >> 3) * 4, c0 = (tid & 7) * 8;

    // stage 1: f_last = relu(bn(feat @ W_proj[3]))
    load_tile(Xs, feat, base, tid);
    load_W(Ws, W_proj + 3 * 4096, tid);
    __syncthreads();
    float accA[4][8] = {};
    gemm64(Xs, Ws, accA, r0, c0);
    float fl[4][8];
#pragma unroll
    for (int j = 0; j < 8; j++) {
        float s = d_sb[6][0][c0 + j], b = d_sb[6][1][c0 + j];
#pragma unroll
        for (int r = 0; r < 4; r++) fl[r][j] = fmaxf(accA[r][j] * s + b, 0.f);
    }
    __syncthreads();
    // stage 2: z += f_last @ W_fuse[0:64]
#pragma unroll
    for (int r = 0; r < 4; r++)
#pragma unroll
        for (int j = 0; j < 8; j++) Xs[(r0 + r) * 64 + c0 + j] = fl[r][j];
    load_W(Ws, W_fuse, tid);
    __syncthreads();
    float z[4][8] = {};
    gemm64(Xs, Ws, z, r0, c0);
    __syncthreads();
    // stage 3: mix into Xs, z += mix @ W_fuse[64:128]
    const float* G0 = d_G;
    const float* G1 = d_G + (size_t)NCL0 * CDIM;
    const float* G2 = d_G + (size_t)(NCL0 + NCL1) * CDIM;
#pragma unroll
    for (int r = 0; r < 4; r++) {
        int m = base + r0 + r;
        if (m < NPTS) {
            float a0 = d_adp[(size_t)m * 3 + 0];
            float a1 = d_adp[(size_t)m * 3 + 1];
            float a2 = d_adp[(size_t)m * 3 + 2];
            size_t cb0 = (size_t)cl0[m] * 64, cb1 = (size_t)cl1[m] * 64, cb2 = (size_t)cl2[m] * 64;
#pragma unroll
            for (int j = 0; j < 8; j++) {
                int c = c0 + j;
                Xs[(r0 + r) * 64 + c] = a0 * G0[cb0 + c] + a1 * G1[cb1 + c] + a2 * G2[cb2 + c];
            }
        } else {
#pragma unroll
            for (int j = 0; j < 8; j++) Xs[(r0 + r) * 64 + c0 + j] = 0.f;
        }
    }
    load_W(Ws, W_fuse + 64 * 64, tid);
    __syncthreads();
    gemm64(Xs, Ws, z, r0, c0);
    __syncthreads();

    // epilogue: write z, reduce column stats (no shared atomics)
    float csum[8] = {}, csq[8] = {};
#pragma unroll
    for (int r = 0; r < 4; r++) {
        int m = base + r0 + r;
        if (m < NPTS) {
#pragma unroll
            for (int j = 0; j < 8; j++) {
                float v = z[r][j];
                d_B1[(size_t)m * 64 + c0 + j] = v;
                csum[j] += v; csq[j] += v * v;
            }
        }
    }
    stat_reduce(Ws, csum, csq, tid, c0, 0);
}

// BN scale/bias from accumulated sum/sumsq
__global__ void k_bnstat(const float* __restrict__ g, const float* __restrict__ b, int q) {
    int c = threadIdx.x;
    if (c < 64) {
        float sum = d_zstat[q * 128 + c];
        float sq = d_zstat[q * 128 + 64 + c];
        float invN = 1.f / (float)NPTS;
        float mean = sum * invN;
        float var = sq * invN - mean * mean;
        float s = g[c] * rsqrtf(var + 1e-3f);
        d_zsb[q][0][c] = s;
        d_zsb[q][1][c] = b[c] - mean * s;
    }
}

// fused = relu(bn(z)) + feat  (B1 -> B2)
__global__ __launch_bounds__(256) void k_applyfuse(const float* __restrict__ feat) {
    long long i = (long long)blockIdx.x * 256 + threadIdx.x;
    if (i >= E4) return;
    long long row = i >> 4;
    int c4 = (int)(i & 15) * 4;
    float4 zv = *(float4*)(d_B1 + row * 64 + c4);
    float4 fv = *(const float4*)(feat + row * 64 + c4);
    float4 o;
    o.x = fmaxf(zv.x * d_zsb[0][0][c4 + 0] + d_zsb[0][1][c4 + 0], 0.f) + fv.x;
    o.y = fmaxf(zv.y * d_zsb[0][0][c4 + 1] + d_zsb[0][1][c4 + 1], 0.f) + fv.y;
    o.z = fmaxf(zv.z * d_zsb[0][0][c4 + 2] + d_zsb[0][1][c4 + 2], 0.f) + fv.z;
    o.w = fmaxf(zv.w * d_zsb[0][0][c4 + 3] + d_zsb[0][1][c4 + 3], 0.f) + fv.w;
    *(float4*)(d_B2 + row * 64 + c4) = o;
}

// submanifold conv: out = sum_k in[nbr[:,k]] @ Wc[k]; mode 0: B2->B1, 1: B1->B3
__global__ __launch_bounds__(256) void k_conv(const int* __restrict__ nbr,
                                              const float* __restrict__ Wc,
                                              int mode, int statq) {
    __shared__ __align__(16) float As[128 * 64];
    __shared__ __align__(16) float Ws[64 * 64];
    const float* fin = (mode == 0) ? d_B2 : d_B1;
    float* fout = (mode == 0) ? d_B1 : d_B3;
    int tid = threadIdx.x, base = blockIdx.x * 128;
    int r0 = (tid >> 3) * 4, c0 = (tid & 7) * 8;
    int gr = tid >> 1, gh = (tid & 1) * 32;
    bool gv = (base + gr) < NPTS;
    float acc[4][8] = {};
    for (int k = 0; k < KTAP; k++) {
        int j = gv ? nbr[(size_t)(base + gr) * KTAP + k] : 0;
        const float4* s = (const float4*)(fin + (size_t)j * 64 + gh);
        float4* d = (float4*)(As + gr * 64 + gh);
#pragma unroll
        for (int i = 0; i < 8; i++) d[i] = s[i];
        load_W(Ws, Wc + k * 4096, tid);
        __syncthreads();
        gemm64(As, Ws, acc, r0, c0);
        __syncthreads();
    }
    // epilogue: write + column stats (no shared atomics)
    float csum[8] = {}, csq[8] = {};
#pragma unroll
    for (int r = 0; r < 4; r++) {
        int m = base + r0 + r;
        if (m < NPTS) {
#pragma unroll
            for (int j = 0; j < 8; j++) {
                float v = acc[r][j];
                fout[(size_t)m * 64 + c0 + j] = v;
                csum[j] += v; csq[j] += v * v;
            }
        }
    }
    stat_reduce(Ws, csum, csq, tid, c0, statq);
}

// B1 = relu(bn(B1)) in place (conv1 BN+relu)
__global__ __launch_bounds__(256) void k_apply1() {
    long long i = (long long)blockIdx.x * 256 + threadIdx.x;
    if (i >= E4) return;
    long long row = i >> 4;
    int c4 = (int)(i & 15) * 4;
    float4 h = *(float4*)(d_B1 + row * 64 + c4);
    h.x = fmaxf(h.x * d_zsb[1][0][c4 + 0] + d_zsb[1][1][c4 + 0], 0.f);
    h.y = fmaxf(h.y * d_zsb[1][0][c4 + 1] + d_zsb[1][1][c4 + 1], 0.f);
    h.z = fmaxf(h.z * d_zsb[1][0][c4 + 2] + d_zsb[1][1][c4 + 2], 0.f);
    h.w = fmaxf(h.w * d_zsb[1][0][c4 + 3] + d_zsb[1][1][c4 + 3], 0.f);
    *(float4*)(d_B1 + row * 64 + c4) = h;
}

// out = relu(bn(h2) + fused)
__global__ __launch_bounds__(256) void k_final(float* __restrict__ out) {
    long long i = (long long)blockIdx.x * 256 + threadIdx.x;
    if (i >= E4) return;
    long long row = i >> 4;
    int c4 = (int)(i & 15) * 4;
    float4 h = *(float4*)(d_B3 + row * 64 + c4);
    float4 r = *(float4*)(d_B2 + row * 64 + c4);
    float4 o;
    o.x = fmaxf(h.x * d_zsb[2][0][c4 + 0] + d_zsb[2][1][c4 + 0] + r.x, 0.f);
    o.y = fmaxf(h.y * d_zsb[2][0][c4 + 1] + d_zsb[2][1][c4 + 1] + r.y, 0.f);
    o.z = fmaxf(h.z * d_zsb[2][0][c4 + 2] + d_zsb[2][1][c4 + 2] + r.z, 0.f);
    o.w = fmaxf(h.w * d_zsb[2][0][c4 + 3] + d_zsb[2][1][c4 + 3] + r.w, 0.f);
    *(float4*)(out + row * 64 + c4) = o;
}

// ---------------------------------------------------------------------------
extern "C" void kernel_launch(void* const* d_in, const int* in_sizes, int n_in,
                              void* d_out, int out_size) {
    (void)in_sizes; (void)n_in; (void)out_size;
    const float* feat   = (const float*)d_in[0];
    const int*   cl0    = (const int*)d_in[1];
    const int*   cl1    = (const int*)d_in[2];
    const int*   cl2    = (const int*)d_in[3];
    const int*   nbr    = (const int*)d_in[4];
    const float* W_lw   = (const float*)d_in[5];
    const float* g_lw   = (const float*)d_in[6];
    const float* b_lw   = (const float*)d_in[7];
    const float* W_w    = (const float*)d_in[8];
    const float* W_proj = (const float*)d_in[9];
    const float* g_proj = (const float*)d_in[10];
    const float* b_proj = (const float*)d_in[11];
    const float* W_adp  = (const float*)d_in[12];
    const float* W_fuse = (const float*)d_in[13];
    const float* g_fuse = (const float*)d_in[14];
    const float* b_fuse = (const float*)d_in[15];
    const float* W_c1   = (const float*)d_in[16];
    const float* g_c1   = (const float*)d_in[17];
    const float* b_c1   = (const float*)d_in[18];
    const float* W_c2   = (const float*)d_in[19];
    const float* g_c2   = (const float*)d_in[20];
    const float* b_c2   = (const float*)d_in[21];
    float* out = (float*)d_out;

    const int ncl[3] = {NCL0, NCL1, NCL2};
    const int* cls[3] = {cl0, cl1, cl2};
    const int e4grid = (E4 + 255) / 256;

    k_zero<<<2048, 256>>>();
    k_gram<<<NT, 256>>>(feat, cl0, cl1, cl2, W_adp);
    k_fold<<<1, 512>>>(W_lw, g_lw, b_lw, W_proj, g_proj, b_proj);

    for (int sc = 0; sc < 3; sc++) {
        k_P<<<NT, 256>>>(feat, W_lw + sc * 4096, cls[sc], sc);
        k_Mw<<<(ncl[sc] + 127) / 128, 256>>>(W_w + sc * 4096, sc, ncl[sc]);
        k_T<<<NT, 256>>>(W_w + sc * 4096, cls[sc], sc);
        k_E<<<e4grid, 256>>>(cls[sc], sc);
        k_F<<<NT, 256>>>(feat, W_proj + sc * 4096, cls[sc], sc);
    }

    k_fuse<<<NT, 256>>>(feat, W_proj, W_fuse, cl0, cl1, cl2);
    k_bnstat<<<1, 64>>>(g_fuse, b_fuse, 0);
    k_applyfuse<<<e4grid, 256>>>(feat);

    k_conv<<<NT, 256>>>(nbr, W_c1, 0, 1);
    k_bnstat<<<1, 64>>>(g_c1, b_c1, 1);
    k_apply1<<<e4grid, 256>>>();

    k_conv<<<NT, 256>>>(nbr, W_c2, 1, 2);
    k_bnstat<<<1, 64>>>(g_c2, b_c2, 2);
    k_final<<<e4grid, 256>>>(out);
}

// round 5
// speedup vs baseline: 1.6704x; 1.6704x over previous
#include <cuda_runtime.h>
#include <cuda_bf16.h>
#include <mma.h>
#include <math.h>
#include <stdint.h>

using namespace nvcuda;

// ---------------------------------------------------------------------------
// OACNN block. N=500000, C=64, K=27, 3 cluster scales.
// Convs: bf16-split (hi+lo) wmma tensor-core GEMMs, K-extended 3-term product.
// Pointwise GEMMs: fp32 SIMT 4x8 register tiles.
// ---------------------------------------------------------------------------

#define NPTS 500000
#define CDIM 64
#define KTAP 27
#define NCL0 4096
#define NCL1 32768
#define NCL2 131072
#define NCLS (NCL0 + NCL1 + NCL2)
#define NT   ((NPTS + 127) / 128)       // 3907 tiles of 128 points
#define E4   (NPTS * 16)                // float4 elements over N*C

#define LDH  72                          // bf16 smem stride (pad)
#define LDC  68                          // fp32 smem stride for conv epilogue
#define SMEMW ((128 * 2 + 64 * 2) * LDH * 2)   // 55296 bytes dynamic smem

// ---- typed device globals, 16B-aligned ----
__device__ __align__(16) float d_S[(size_t)NCLS * CDIM];
__device__ __align__(16) float d_D[(size_t)NCLS * CDIM];
__device__ __align__(16) float d_G[(size_t)NCLS * CDIM];
__device__ __align__(16) float d_B1[(size_t)NPTS * CDIM];
__device__ __align__(16) float d_B2[(size_t)NPTS * CDIM];
__device__ __align__(16) float d_B3[(size_t)NPTS * CDIM];
__device__ __align__(16) float d_Mw[(size_t)NCL2 * CDIM];
__device__ __align__(16) __nv_bfloat16 d_Hc[(size_t)NPTS * CDIM];  // conv input hi
__device__ __align__(16) __nv_bfloat16 d_Lc[(size_t)NPTS * CDIM];  // conv input lo
__device__ __align__(16) __nv_bfloat16 d_Whi[KTAP * CDIM * CDIM];
__device__ __align__(16) __nv_bfloat16 d_Wlo[KTAP * CDIM * CDIM];
__device__ __align__(16) float d_cntf[NCLS];
__device__ __align__(16) float d_gram[CDIM * CDIM];
__device__ __align__(16) float d_cs[CDIM];
__device__ __align__(16) float d_zstat[3 * 2 * CDIM];
__device__ __align__(16) float d_adp[(size_t)NPTS * 3];
__device__ __align__(16) float d_sb[7][2][CDIM];
__device__ __align__(16) float d_zsb[3][2][CDIM];
__device__ __align__(16) unsigned int d_gmaxu[4];

__device__ __forceinline__ int clpre(int sc) {
    return sc == 0 ? 0 : (sc == 1 ? NCL0 : (NCL0 + NCL1));
}
__device__ __forceinline__ unsigned int fkey(float v) {
    unsigned int b = __float_as_uint(v);
    return (b & 0x80000000u) ? ~b : (b ^ 0x80000000u);
}
__device__ __forceinline__ float funkey(unsigned int u) {
    unsigned int b = (u & 0x80000000u) ? (u ^ 0x80000000u) : ~u;
    return __uint_as_float(b);
}

// 128x64 @ 64x64 SIMT GEMM, thread = 4 rows x 8 cols
__device__ __forceinline__ void gemm64(const float* __restrict__ Xs,
                                       const float* __restrict__ Ws,
                                       float acc[4][8], int r0, int c0) {
#pragma unroll
    for (int cc = 0; cc < 64; cc += 4) {
        float4 a4[4];
#pragma unroll
        for (int r = 0; r < 4; r++) a4[r] = *(const float4*)(Xs + (r0 + r) * 64 + cc);
#pragma unroll
        for (int u = 0; u < 4; u++) {
            float4 w0 = *(const float4*)(Ws + (cc + u) * 64 + c0);
            float4 w1 = *(const float4*)(Ws + (cc + u) * 64 + c0 + 4);
#pragma unroll
            for (int r = 0; r < 4; r++) {
                float a = (u == 0) ? a4[r].x : (u == 1) ? a4[r].y : (u == 2) ? a4[r].z : a4[r].w;
                acc[r][0] += a * w0.x; acc[r][1] += a * w0.y;
                acc[r][2] += a * w0.z; acc[r][3] += a * w0.w;
                acc[r][4] += a * w1.x; acc[r][5] += a * w1.y;
                acc[r][6] += a * w1.z; acc[r][7] += a * w1.w;
            }
        }
    }
}

__device__ __forceinline__ void load_tile(float* Xs, const float* __restrict__ src,
                                          int base, int tid) {
    int r = tid >> 1, h = (tid & 1) * 32;
    bool v = (base + r) < NPTS;
    const float4* s = (const float4*)(src + (size_t)(base + r) * 64 + h);
    float4* d = (float4*)(Xs + r * 64 + h);
    float4 z = make_float4(0.f, 0.f, 0.f, 0.f);
#pragma unroll
    for (int i = 0; i < 8; i++) d[i] = v ? s[i] : z;
}

__device__ __forceinline__ void load_W(float* Ws, const float* __restrict__ src, int tid) {
    const float4* s = (const float4*)src;
    float4* d = (float4*)Ws;
#pragma unroll
    for (int i = 0; i < 4; i++) d[tid + i * 256] = s[tid + i * 256];
}

// BN-stat epilogue reduction (no shared atomics); scratch >= 4096 floats
__device__ __forceinline__ void stat_reduce(float* scratch, const float csum[8],
                                            const float csq[8], int tid, int c0,
                                            int statq) {
    int rg = tid >> 3;
#pragma unroll
    for (int j = 0; j < 8; j++) {
        scratch[rg * 64 + c0 + j] = csum[j];
        scratch[2048 + rg * 64 + c0 + j] = csq[j];
    }
    __syncthreads();
    if (tid < 128) {
        int part = tid >> 6;
        int c = tid & 63;
        const float* p = scratch + part * 2048 + c;
        float tot = 0.f;
#pragma unroll
        for (int rg2 = 0; rg2 < 32; rg2++) tot += p[rg2 * 64];
        atomicAdd(&d_zstat[statq * 128 + part * 64 + c], tot);
    }
}

// ---------------------------------------------------------------------------
__global__ __launch_bounds__(256) void k_zero() {
    long long i = (long long)blockIdx.x * 256 + threadIdx.x;
    long long stride = (long long)gridDim.x * 256;
    const long long nS = (long long)NCLS * CDIM;
    for (long long idx = i; idx < nS; idx += stride) {
        d_S[idx] = 0.f; d_D[idx] = 0.f; d_G[idx] = 0.f;
    }
    for (long long idx = i; idx < NCLS; idx += stride) d_cntf[idx] = 0.f;
    if (i < 4096) d_gram[i] = 0.f;
    if (i < 64) d_cs[i] = 0.f;
    if (i < 384) d_zstat[i] = 0.f;
    if (i < 3) d_gmaxu[i] = 0x007FFFFFu;
}

// Gram + column sums + cluster counts + adp softmax
__global__ __launch_bounds__(256) void k_gram(const float* __restrict__ feat,
                                              const int* __restrict__ cl0,
                                              const int* __restrict__ cl1,
                                              const int* __restrict__ cl2,
                                              const float* __restrict__ W_adp) {
    __shared__ __align__(16) float Xs[128 * 64];
    __shared__ float Was[CDIM * 3];
    int tid = threadIdx.x;
    int base = blockIdx.x * 128;
    load_tile(Xs, feat, base, tid);
    if (tid < CDIM * 3) Was[tid] = W_adp[tid];
    __syncthreads();

    if (tid < 128 && base + tid < NPTS) {
        int n = base + tid;
        atomicAdd(&d_cntf[cl0[n]], 1.f);
        atomicAdd(&d_cntf[NCL0 + cl1[n]], 1.f);
        atomicAdd(&d_cntf[NCL0 + NCL1 + cl2[n]], 1.f);
        float a0 = 0.f, a1 = 0.f, a2 = 0.f;
#pragma unroll 8
        for (int c = 0; c < 64; c++) {
            float x = Xs[tid * 64 + c];
            a0 += x * Was[c * 3 + 0];
            a1 += x * Was[c * 3 + 1];
            a2 += x * Was[c * 3 + 2];
        }
        float mx = fmaxf(a0, fmaxf(a1, a2));
        float e0 = expf(a0 - mx), e1 = expf(a1 - mx), e2 = expf(a2 - mx);
        float inv = 1.f / (e0 + e1 + e2);
        d_adp[(size_t)n * 3 + 0] = e0 * inv;
        d_adp[(size_t)n * 3 + 1] = e1 * inv;
        d_adp[(size_t)n * 3 + 2] = e2 * inv;
    }

    int i = tid & 63;
    int j0 = (tid >> 6) * 16;
    float acc[16];
#pragma unroll
    for (int q = 0; q < 16; q++) acc[q] = 0.f;
    for (int m = 0; m < 128; m++) {
        float a = Xs[m * 64 + i];
        const float4* xr = (const float4*)(Xs + m * 64 + j0);
#pragma unroll
        for (int q = 0; q < 4; q++) {
            float4 w = xr[q];
            acc[q * 4 + 0] += a * w.x; acc[q * 4 + 1] += a * w.y;
            acc[q * 4 + 2] += a * w.z; acc[q * 4 + 3] += a * w.w;
        }
    }
#pragma unroll
    for (int q = 0; q < 16; q++)
        atomicAdd(&d_gram[i * 64 + j0 + q], acc[q]);

    if (tid < 64) {
        float s = 0.f;
        for (int m = 0; m < 128; m++) s += Xs[m * 64 + tid];
        atomicAdd(&d_cs[tid], s);
    }
}

// fold BN of (feat @ W) into scale/bias via Gram trick
__global__ __launch_bounds__(512) void k_fold(const float* __restrict__ W_lw,
                                              const float* __restrict__ g_lw,
                                              const float* __restrict__ b_lw,
                                              const float* __restrict__ W_proj,
                                              const float* __restrict__ g_proj,
                                              const float* __restrict__ b_proj) {
    __shared__ __align__(16) float Gs[64 * 64];
    __shared__ float cs[64];
    int tid = threadIdx.x;
    for (int idx = tid; idx < 4096; idx += blockDim.x) Gs[idx] = d_gram[idx];
    if (tid < 64) cs[tid] = d_cs[tid];
    __syncthreads();
    if (tid < 448) {
        int q = tid >> 6, j = tid & 63;
        const float* W = q < 3 ? W_lw + q * 4096 : W_proj + (q - 3) * 4096;
        const float* g = q < 3 ? g_lw + q * 64 : g_proj + (q - 3) * 64;
        const float* b = q < 3 ? b_lw + q * 64 : b_proj + (q - 3) * 64;
        float wcol[64];
        for (int i = 0; i < 64; i++) wcol[i] = W[i * 64 + j];
        float mean = 0.f, m2 = 0.f;
        for (int i = 0; i < 64; i++) {
            mean += cs[i] * wcol[i];
            float t = 0.f;
            for (int i2 = 0; i2 < 64; i2++) t += Gs[i * 64 + i2] * wcol[i2];
            m2 += wcol[i] * t;
        }
        float invN = 1.f / (float)NPTS;
        mean *= invN; m2 *= invN;
        float var = m2 - mean * mean;
        float s = g[j] * rsqrtf(var + 1e-3f);
        d_sb[q][0][j] = s;
        d_sb[q][1][j] = b[j] - mean * s;
    }
}

// P = relu(bn(feat@W_lw)) [smem only]; S[cl]+=P; U = P@W_w -> B2
__global__ __launch_bounds__(256) void k_PU(const float* __restrict__ feat,
                                            const float* __restrict__ Wlw,
                                            const float* __restrict__ Ww,
                                            const int* __restrict__ cl, int sc) {
    __shared__ __align__(16) float Xs[128 * 64];
    __shared__ __align__(16) float Ws[64 * 64];
    int tid = threadIdx.x, base = blockIdx.x * 128;
    load_tile(Xs, feat, base, tid);
    load_W(Ws, Wlw, tid);
    __syncthreads();
    int r0 = (tid >> 3) * 4, c0 = (tid & 7) * 8;
    float acc[4][8] = {};
    gemm64(Xs, Ws, acc, r0, c0);
    float* S = d_S + (size_t)clpre(sc) * CDIM;
    float y[4][8];
#pragma unroll
    for (int j = 0; j < 8; j++) {
        float s = d_sb[sc][0][c0 + j], b = d_sb[sc][1][c0 + j];
#pragma unroll
        for (int r = 0; r < 4; r++) y[r][j] = fmaxf(acc[r][j] * s + b, 0.f);
    }
#pragma unroll
    for (int r = 0; r < 4; r++) {
        int m = base + r0 + r;
        if (m < NPTS) {
            size_t cb = (size_t)cl[m] * 64;
#pragma unroll
            for (int j = 0; j < 8; j++) atomicAdd(&S[cb + c0 + j], y[r][j]);
        }
    }
    __syncthreads();               // gemm1 reads of Xs done
#pragma unroll
    for (int r = 0; r < 4; r++)
#pragma unroll
        for (int j = 0; j < 8; j++) Xs[(r0 + r) * 64 + c0 + j] = y[r][j];
    load_W(Ws, Ww, tid);
    __syncthreads();
    float acc2[4][8] = {};
    gemm64(Xs, Ws, acc2, r0, c0);
#pragma unroll
    for (int r = 0; r < 4; r++) {
        int m = base + r0 + r;
        if (m < NPTS)
#pragma unroll
            for (int j = 0; j < 8; j++) d_B2[(size_t)m * 64 + c0 + j] = acc2[r][j];
    }
}

// Mw[c] = (S[c]/max(cnt,1)) @ W_w
__global__ __launch_bounds__(256) void k_Mw(const float* __restrict__ Ww, int sc, int ncl) {
    __shared__ __align__(16) float Xs[128 * 64];
    __shared__ __align__(16) float Ws[64 * 64];
    int tid = threadIdx.x, base = blockIdx.x * 128;
    const float* S = d_S + (size_t)clpre(sc) * CDIM;
    const float* cnt = d_cntf + clpre(sc);
    {
        int r = tid >> 1, h = (tid & 1) * 32;
        int cr = base + r;
        bool v = cr < ncl;
        float inv = 0.f;
        if (v) inv = 1.f / fmaxf(cnt[cr], 1.f);
        const float4* s4 = (const float4*)(S + (size_t)cr * 64 + h);
        float4* dd = (float4*)(Xs + r * 64 + h);
        float4 z = make_float4(0.f, 0.f, 0.f, 0.f);
#pragma unroll
        for (int i = 0; i < 8; i++) {
            float4 x = v ? s4[i] : z;
            x.x *= inv; x.y *= inv; x.z *= inv; x.w *= inv;
            dd[i] = x;
        }
    }
    load_W(Ws, Ww, tid);
    __syncthreads();
    int r0 = (tid >> 3) * 4, c0 = (tid & 7) * 8;
    float acc[4][8] = {};
    gemm64(Xs, Ws, acc, r0, c0);
#pragma unroll
    for (int r = 0; r < 4; r++) {
        int m = base + r0 + r;
        if (m < ncl)
#pragma unroll
            for (int j = 0; j < 8; j++) d_Mw[(size_t)m * 64 + c0 + j] = acc[r][j];
    }
}

// T = U - Mw[cl] (in-place B2); global max -> d_gmaxu[sc]
__global__ __launch_bounds__(256) void k_maxU(const int* __restrict__ cl, int sc) {
    long long i = (long long)blockIdx.x * 256 + threadIdx.x;
    float lmax = -3.402823466e38f;
    if (i < E4) {
        long long row = i >> 4;
        int c4 = (int)(i & 15) * 4;
        float4 u = *(float4*)(d_B2 + row * 64 + c4);
        size_t cb = (size_t)cl[row] * 64 + c4;
        float4 m = *(const float4*)(d_Mw + cb);
        float4 t;
        t.x = u.x - m.x; t.y = u.y - m.y; t.z = u.z - m.z; t.w = u.w - m.w;
        *(float4*)(d_B2 + row * 64 + c4) = t;
        lmax = fmaxf(fmaxf(t.x, t.y), fmaxf(t.z, t.w));
    }
#pragma unroll
    for (int off = 16; off > 0; off >>= 1)
        lmax = fmaxf(lmax, __shfl_xor_sync(0xFFFFFFFFu, lmax, off));
    if ((threadIdx.x & 31) == 0) atomicMax(&d_gmaxu[sc], fkey(lmax));
}

// E = exp(T - max); D[cl] += E; in-place B2
__global__ __launch_bounds__(256) void k_E(const int* __restrict__ cl, int sc) {
    long long i = (long long)blockIdx.x * 256 + threadIdx.x;
    if (i >= E4) return;
    long long row = i >> 4;
    int c4 = (int)(i & 15) * 4;
    float M = funkey(d_gmaxu[sc]);
    float* D = d_D + (size_t)clpre(sc) * CDIM;
    float4 t = *(float4*)(d_B2 + row * 64 + c4);
    float4 e;
    e.x = expf(t.x - M); e.y = expf(t.y - M);
    e.z = expf(t.z - M); e.w = expf(t.w - M);
    *(float4*)(d_B2 + row * 64 + c4) = e;
    size_t cb = (size_t)cl[row] * 64 + c4;
    atomicAdd(&D[cb + 0], e.x); atomicAdd(&D[cb + 1], e.y);
    atomicAdd(&D[cb + 2], e.z); atomicAdd(&D[cb + 3], e.w);
}

// F = relu(bn(feat@W_proj)); G[cl] += F * E / (D[cl]+1e-6)
__global__ __launch_bounds__(256) void k_F(const float* __restrict__ feat,
                                           const float* __restrict__ Wp,
                                           const int* __restrict__ cl, int sc) {
    __shared__ __align__(16) float Xs[128 * 64];
    __shared__ __align__(16) float Ws[64 * 64];
    int tid = threadIdx.x, base = blockIdx.x * 128;
    load_tile(Xs, feat, base, tid);
    load_W(Ws, Wp, tid);
    __syncthreads();
    int r0 = (tid >> 3) * 4, c0 = (tid & 7) * 8;
    float acc[4][8] = {};
    gemm64(Xs, Ws, acc, r0, c0);
    int sb = 3 + sc;
    float* D = d_D + (size_t)clpre(sc) * CDIM;
    float* G = d_G + (size_t)clpre(sc) * CDIM;
    float s[8], b[8];
#pragma unroll
    for (int j = 0; j < 8; j++) { s[j] = d_sb[sb][0][c0 + j]; b[j] = d_sb[sb][1][c0 + j]; }
#pragma unroll
    for (int r = 0; r < 4; r++) {
        int m = base + r0 + r;
        if (m < NPTS) {
            size_t cb = (size_t)cl[m] * 64;
#pragma unroll
            for (int j = 0; j < 8; j++) {
                float F = fmaxf(acc[r][j] * s[j] + b[j], 0.f);
                float e = d_B2[(size_t)m * 64 + c0 + j];
                float dn = D[cb + c0 + j] + 1e-6f;
                atomicAdd(&G[cb + c0 + j], F * e / dn);
            }
        }
    }
}

// z = [f_last, mix] @ W_fuse -> B1; fuse BN stats
__global__ __launch_bounds__(256) void k_fuse(const float* __restrict__ feat,
                                              const float* __restrict__ W_proj,
                                              const float* __restrict__ W_fuse,
                                              const int* __restrict__ cl0,
                                              const int* __restrict__ cl1,
                                              const int* __restrict__ cl2) {
    __shared__ __align__(16) float Xs[128 * 64];
    __shared__ __align__(16) float Ws[64 * 64];
    int tid = threadIdx.x, base = blockIdx.x * 128;
    int r0 = (tid >> 3) * 4, c0 = (tid & 7) * 8;

    load_tile(Xs, feat, base, tid);
    load_W(Ws, W_proj + 3 * 4096, tid);
    __syncthreads();
    float accA[4][8] = {};
    gemm64(Xs, Ws, accA, r0, c0);
    float fl[4][8];
#pragma unroll
    for (int j = 0; j < 8; j++) {
        float s = d_sb[6][0][c0 + j], b = d_sb[6][1][c0 + j];
#pragma unroll
        for (int r = 0; r < 4; r++) fl[r][j] = fmaxf(accA[r][j] * s + b, 0.f);
    }
    __syncthreads();
#pragma unroll
    for (int r = 0; r < 4; r++)
#pragma unroll
        for (int j = 0; j < 8; j++) Xs[(r0 + r) * 64 + c0 + j] = fl[r][j];
    load_W(Ws, W_fuse, tid);
    __syncthreads();
    float z[4][8] = {};
    gemm64(Xs, Ws, z, r0, c0);
    __syncthreads();
    const float* G0 = d_G;
    const float* G1 = d_G + (size_t)NCL0 * CDIM;
    const float* G2 = d_G + (size_t)(NCL0 + NCL1) * CDIM;
#pragma unroll
    for (int r = 0; r < 4; r++) {
        int m = base + r0 + r;
        if (m < NPTS) {
            float a0 = d_adp[(size_t)m * 3 + 0];
            float a1 = d_adp[(size_t)m * 3 + 1];
            float a2 = d_adp[(size_t)m * 3 + 2];
            size_t cb0 = (size_t)cl0[m] * 64, cb1 = (size_t)cl1[m] * 64, cb2 = (size_t)cl2[m] * 64;
#pragma unroll
            for (int j = 0; j < 8; j++) {
                int c = c0 + j;
                Xs[(r0 + r) * 64 + c] = a0 * G0[cb0 + c] + a1 * G1[cb1 + c] + a2 * G2[cb2 + c];
            }
        } else {
#pragma unroll
            for (int j = 0; j < 8; j++) Xs[(r0 + r) * 64 + c0 + j] = 0.f;
        }
    }
    load_W(Ws, W_fuse + 64 * 64, tid);
    __syncthreads();
    gemm64(Xs, Ws, z, r0, c0);
    __syncthreads();

    float csum[8] = {}, csq[8] = {};
#pragma unroll
    for (int r = 0; r < 4; r++) {
        int m = base + r0 + r;
        if (m < NPTS) {
#pragma unroll
            for (int j = 0; j < 8; j++) {
                float v = z[r][j];
                d_B1[(size_t)m * 64 + c0 + j] = v;
                csum[j] += v; csq[j] += v * v;
            }
        }
    }
    stat_reduce(Ws, csum, csq, tid, c0, 0);
}

__global__ void k_bnstat(const float* __restrict__ g, const float* __restrict__ b, int q) {
    int c = threadIdx.x;
    if (c < 64) {
        float sum = d_zstat[q * 128 + c];
        float sq = d_zstat[q * 128 + 64 + c];
        float invN = 1.f / (float)NPTS;
        float mean = sum * invN;
        float var = sq * invN - mean * mean;
        float s = g[c] * rsqrtf(var + 1e-3f);
        d_zsb[q][0][c] = s;
        d_zsb[q][1][c] = b[c] - mean * s;
    }
}

__device__ __forceinline__ void split1(float v, __nv_bfloat16* H, __nv_bfloat16* L) {
    __nv_bfloat16 h = __float2bfloat16(v);
    *H = h;
    *L = __float2bfloat16(v - __bfloat162float(h));
}

// fused = relu(bn(z)) + feat -> B2 (fp32) + hi/lo bf16 split (conv1 input)
__global__ __launch_bounds__(256) void k_applyfuse(const float* __restrict__ feat) {
    long long i = (long long)blockIdx.x * 256 + threadIdx.x;
    if (i >= E4) return;
    long long row = i >> 4;
    int c4 = (int)(i & 15) * 4;
    float4 zv = *(float4*)(d_B1 + row * 64 + c4);
    float4 fv = *(const float4*)(feat + row * 64 + c4);
    float4 o;
    o.x = fmaxf(zv.x * d_zsb[0][0][c4 + 0] + d_zsb[0][1][c4 + 0], 0.f) + fv.x;
    o.y = fmaxf(zv.y * d_zsb[0][0][c4 + 1] + d_zsb[0][1][c4 + 1], 0.f) + fv.y;
    o.z = fmaxf(zv.z * d_zsb[0][0][c4 + 2] + d_zsb[0][1][c4 + 2], 0.f) + fv.z;
    o.w = fmaxf(zv.w * d_zsb[0][0][c4 + 3] + d_zsb[0][1][c4 + 3], 0.f) + fv.w;
    size_t p = row * 64 + c4;
    *(float4*)(d_B2 + p) = o;
    split1(o.x, d_Hc + p + 0, d_Lc + p + 0);
    split1(o.y, d_Hc + p + 1, d_Lc + p + 1);
    split1(o.z, d_Hc + p + 2, d_Lc + p + 2);
    split1(o.w, d_Hc + p + 3, d_Lc + p + 3);
}

// B1 = relu(bn(B1)) in place + hi/lo split (conv2 input)
__global__ __launch_bounds__(256) void k_apply1() {
    long long i = (long long)blockIdx.x * 256 + threadIdx.x;
    if (i >= E4) return;
    long long row = i >> 4;
    int c4 = (int)(i & 15) * 4;
    float4 h = *(float4*)(d_B1 + row * 64 + c4);
    h.x = fmaxf(h.x * d_zsb[1][0][c4 + 0] + d_zsb[1][1][c4 + 0], 0.f);
    h.y = fmaxf(h.y * d_zsb[1][0][c4 + 1] + d_zsb[1][1][c4 + 1], 0.f);
    h.z = fmaxf(h.z * d_zsb[1][0][c4 + 2] + d_zsb[1][1][c4 + 2], 0.f);
    h.w = fmaxf(h.w * d_zsb[1][0][c4 + 3] + d_zsb[1][1][c4 + 3], 0.f);
    size_t p = row * 64 + c4;
    *(float4*)(d_B1 + p) = h;
    split1(h.x, d_Hc + p + 0, d_Lc + p + 0);
    split1(h.y, d_Hc + p + 1, d_Lc + p + 1);
    split1(h.z, d_Hc + p + 2, d_Lc + p + 2);
    split1(h.w, d_Hc + p + 3, d_Lc + p + 3);
}

// split conv weights fp32 -> (hi, lo) bf16
__global__ __launch_bounds__(256) void k_cvtW(const float* __restrict__ W) {
    int i = blockIdx.x * 256 + threadIdx.x;
    if (i < KTAP * 4096) split1(W[i], d_Whi + i, d_Wlo + i);
}

// submanifold conv, bf16-split wmma. out = sum_k in[nbr[:,k]] @ Wc[k]
// in = (d_Hc, d_Lc); out = B1 (mode 0) or B3 (mode 1); raw outputs + BN stats.
__global__ __launch_bounds__(256) void k_convw(const int* __restrict__ nbr,
                                               int mode, int statq) {
    extern __shared__ __align__(16) char smraw[];
    __nv_bfloat16* Ah = (__nv_bfloat16*)smraw;           // 128 x LDH
    __nv_bfloat16* Al = Ah + 128 * LDH;
    __nv_bfloat16* Wh = Al + 128 * LDH;                  // 64 x LDH
    __nv_bfloat16* Wl = Wh + 64 * LDH;
    float* Cs = (float*)smraw;                           // epilogue reuse, stride LDC

    int tid = threadIdx.x, base = blockIdx.x * 128;
    int warp = tid >> 5;
    int gr = tid >> 1, gh = (tid & 1) * 32;              // row, bf16 col offset
    bool gv = (base + gr) < NPTS;

    uint4 pah[4], pal[4], pwh[2], pwl[2];
    auto prefA = [&](int k) {
        int j = gv ? nbr[(size_t)(base + gr) * KTAP + k] : 0;
        const uint4* sh = (const uint4*)(d_Hc + (size_t)j * 64 + gh);
        const uint4* sl = (const uint4*)(d_Lc + (size_t)j * 64 + gh);
#pragma unroll
        for (int i = 0; i < 4; i++) { pah[i] = sh[i]; pal[i] = sl[i]; }
    };
    auto prefW = [&](int k) {
        const uint4* swh = (const uint4*)(d_Whi + (size_t)k * 4096);
        const uint4* swl = (const uint4*)(d_Wlo + (size_t)k * 4096);
#pragma unroll
        for (int i = 0; i < 2; i++) { pwh[i] = swh[tid + i * 256]; pwl[i] = swl[tid + i * 256]; }
    };

    wmma::fragment<wmma::accumulator, 16, 16, 16, float> cf[4];
#pragma unroll
    for (int n = 0; n < 4; n++) wmma::fill_fragment(cf[n], 0.f);

    prefA(0); prefW(0);
    for (int k = 0; k < KTAP; k++) {
        __syncthreads();                                  // previous mma done
        {
            uint4* dh = (uint4*)(Ah + gr * LDH + gh);
            uint4* dl = (uint4*)(Al + gr * LDH + gh);
#pragma unroll
            for (int i = 0; i < 4; i++) { dh[i] = pah[i]; dl[i] = pal[i]; }
#pragma unroll
            for (int i = 0; i < 2; i++) {
                int flat8 = (tid + i * 256) * 8;
                int row = flat8 >> 6, col = flat8 & 63;
                *(uint4*)(Wh + row * LDH + col) = pwh[i];
                *(uint4*)(Wl + row * LDH + col) = pwl[i];
            }
        }
        __syncthreads();                                  // tiles ready
        if (k + 1 < KTAP) { prefA(k + 1); prefW(k + 1); } // overlap with mma

        // 3-term split: Ahi*Whi + Alo*Whi + Ahi*Wlo
#pragma unroll
        for (int s = 0; s < 3; s++) {
            const __nv_bfloat16* Ab = ((s == 1) ? Al : Ah) + warp * 16 * LDH;
            const __nv_bfloat16* Bb = (s == 2) ? Wl : Wh;
#pragma unroll
            for (int kk = 0; kk < 64; kk += 16) {
                wmma::fragment<wmma::matrix_a, 16, 16, 16, __nv_bfloat16, wmma::row_major> af;
                wmma::load_matrix_sync(af, Ab + kk, LDH);
#pragma unroll
                for (int n = 0; n < 4; n++) {
                    wmma::fragment<wmma::matrix_b, 16, 16, 16, __nv_bfloat16, wmma::row_major> bf_;
                    wmma::load_matrix_sync(bf_, Bb + kk * LDH + n * 16, LDH);
                    wmma::mma_sync(cf[n], af, bf_, cf[n]);
                }
            }
        }
    }
    __syncthreads();
#pragma unroll
    for (int n = 0; n < 4; n++)
        wmma::store_matrix_sync(Cs + warp * 16 * LDC + n * 16, cf[n], LDC, wmma::mem_row_major);
    __syncthreads();

    float* fout = (mode == 0) ? d_B1 : d_B3;
    int r0 = (tid >> 3) * 4, c0 = (tid & 7) * 8;
    float csum[8] = {}, csq[8] = {};
#pragma unroll
    for (int r = 0; r < 4; r++) {
        int m = base + r0 + r;
        if (m < NPTS) {
            float4 v0 = *(float4*)(Cs + (r0 + r) * LDC + c0);
            float4 v1 = *(float4*)(Cs + (r0 + r) * LDC + c0 + 4);
            *(float4*)(fout + (size_t)m * 64 + c0) = v0;
            *(float4*)(fout + (size_t)m * 64 + c0 + 4) = v1;
            csum[0] += v0.x; csq[0] += v0.x * v0.x;
            csum[1] += v0.y; csq[1] += v0.y * v0.y;
            csum[2] += v0.z; csq[2] += v0.z * v0.z;
            csum[3] += v0.w; csq[3] += v0.w * v0.w;
            csum[4] += v1.x; csq[4] += v1.x * v1.x;
            csum[5] += v1.y; csq[5] += v1.y * v1.y;
            csum[6] += v1.z; csq[6] += v1.z * v1.z;
            csum[7] += v1.w; csq[7] += v1.w * v1.w;
        }
    }
    stat_reduce(Cs + 128 * LDC, csum, csq, tid, c0, statq);
}

// out = relu(bn(h2) + fused)
__global__ __launch_bounds__(256) void k_final(float* __restrict__ out) {
    long long i = (long long)blockIdx.x * 256 + threadIdx.x;
    if (i >= E4) return;
    long long row = i >> 4;
    int c4 = (int)(i & 15) * 4;
    float4 h = *(float4*)(d_B3 + row * 64 + c4);
    float4 r = *(float4*)(d_B2 + row * 64 + c4);
    float4 o;
    o.x = fmaxf(h.x * d_zsb[2][0][c4 + 0] + d_zsb[2][1][c4 + 0] + r.x, 0.f);
    o.y = fmaxf(h.y * d_zsb[2][0][c4 + 1] + d_zsb[2][1][c4 + 1] + r.y, 0.f);
    o.z = fmaxf(h.z * d_zsb[2][0][c4 + 2] + d_zsb[2][1][c4 + 2] + r.z, 0.f);
    o.w = fmaxf(h.w * d_zsb[2][0][c4 + 3] + d_zsb[2][1][c4 + 3] + r.w, 0.f);
    *(float4*)(out + row * 64 + c4) = o;
}

// ---------------------------------------------------------------------------
extern "C" void kernel_launch(void* const* d_in, const int* in_sizes, int n_in,
                              void* d_out, int out_size) {
    (void)in_sizes; (void)n_in; (void)out_size;
    const float* feat   = (const float*)d_in[0];
    const int*   cl0    = (const int*)d_in[1];
    const int*   cl1    = (const int*)d_in[2];
    const int*   cl2    = (const int*)d_in[3];
    const int*   nbr    = (const int*)d_in[4];
    const float* W_lw   = (const float*)d_in[5];
    const float* g_lw   = (const float*)d_in[6];
    const float* b_lw   = (const float*)d_in[7];
    const float* W_w    = (const float*)d_in[8];
    const float* W_proj = (const float*)d_in[9];
    const float* g_proj = (const float*)d_in[10];
    const float* b_proj = (const float*)d_in[11];
    const float* W_adp  = (const float*)d_in[12];
    const float* W_fuse = (const float*)d_in[13];
    const float* g_fuse = (const float*)d_in[14];
    const float* b_fuse = (const float*)d_in[15];
    const float* W_c1   = (const float*)d_in[16];
    const float* g_c1   = (const float*)d_in[17];
    const float* b_c1   = (const float*)d_in[18];
    const float* W_c2   = (const float*)d_in[19];
    const float* g_c2   = (const float*)d_in[20];
    const float* b_c2   = (const float*)d_in[21];
    float* out = (float*)d_out;

    cudaFuncSetAttribute(k_convw, cudaFuncAttributeMaxDynamicSharedMemorySize, SMEMW);

    const int ncl[3] = {NCL0, NCL1, NCL2};
    const int* cls[3] = {cl0, cl1, cl2};
    const int e4grid = (E4 + 255) / 256;
    const int wgrid = (KTAP * 4096 + 255) / 256;

    k_zero<<<2048, 256>>>();
    k_gram<<<NT, 256>>>(feat, cl0, cl1, cl2, W_adp);
    k_fold<<<1, 512>>>(W_lw, g_lw, b_lw, W_proj, g_proj, b_proj);

    for (int sc = 0; sc < 3; sc++) {
        k_PU<<<NT, 256>>>(feat, W_lw + sc * 4096, W_w + sc * 4096, cls[sc], sc);
        k_Mw<<<(ncl[sc] + 127) / 128, 256>>>(W_w + sc * 4096, sc, ncl[sc]);
        k_maxU<<<e4grid, 256>>>(cls[sc], sc);
        k_E<<<e4grid, 256>>>(cls[sc], sc);
        k_F<<<NT, 256>>>(feat, W_proj + sc * 4096, cls[sc], sc);
    }

    k_fuse<<<NT, 256>>>(feat, W_proj, W_fuse, cl0, cl1, cl2);
    k_bnstat<<<1, 64>>>(g_fuse, b_fuse, 0);
    k_applyfuse<<<e4grid, 256>>>(feat);

    k_cvtW<<<wgrid, 256>>>(W_c1);
    k_convw<<<NT, 256, SMEMW>>>(nbr, 0, 1);
    k_bnstat<<<1, 64>>>(g_c1, b_c1, 1);
    k_apply1<<<e4grid, 256>>>();

    k_cvtW<<<wgrid, 256>>>(W_c2);
    k_convw<<<NT, 256, SMEMW>>>(nbr, 1, 2);
    k_bnstat<<<1, 64>>>(g_c2, b_c2, 2);
    k_final<<<e4grid, 256>>>(out);
}

// round 8
// speedup vs baseline: 1.8503x; 1.1077x over previous
#include <cuda_runtime.h>
#include <cuda_bf16.h>
#include <mma.h>
#include <math.h>
#include <stdint.h>

using namespace nvcuda;

// ---------------------------------------------------------------------------
// OACNN block. N=500000, C=64, K=27, 3 cluster scales.
// ALL dense GEMMs (pointwise + convs) on tensor cores via bf16-split (hi+lo)
// 3-term products. Epilogues (BN, relu, segment atomics) fused.
// ---------------------------------------------------------------------------

#define NPTS 500000
#define CDIM 64
#define KTAP 27
#define NCL0 4096
#define NCL1 32768
#define NCL2 131072
#define NCLS (NCL0 + NCL1 + NCL2)
#define NT   ((NPTS + 127) / 128)
#define E4   (NPTS * 16)

#define LDH  72                          // bf16 smem stride
#define LDC  68                          // fp32 smem stride
#define SMEMW ((128 * 2 + 64 * 2) * LDH * 2)            // conv kernel smem
#define SMEMP (2 * 128 * LDH * 2 + 128 * LDC * 4 + 16384) // pointwise kernels

typedef __nv_bfloat16 bf16;

// ---- device globals, 16B-aligned ----
__device__ __align__(16) float d_S[(size_t)NCLS * CDIM];
__device__ __align__(16) float d_D[(size_t)NCLS * CDIM];
__device__ __align__(16) float d_G[(size_t)NCLS * CDIM];
__device__ __align__(16) float d_B1[(size_t)NPTS * CDIM];
__device__ __align__(16) float d_B2[(size_t)NPTS * CDIM];
__device__ __align__(16) float d_B3[(size_t)NPTS * CDIM];
__device__ __align__(16) float d_Mw[(size_t)NCL2 * CDIM];
__device__ __align__(16) bf16 d_Fh[(size_t)NPTS * CDIM];   // feat hi
__device__ __align__(16) bf16 d_Fl[(size_t)NPTS * CDIM];   // feat lo
__device__ __align__(16) bf16 d_Hc[(size_t)NPTS * CDIM];   // conv input hi
__device__ __align__(16) bf16 d_Lc[(size_t)NPTS * CDIM];   // conv input lo
__device__ __align__(16) bf16 d_Whi[KTAP * CDIM * CDIM];
__device__ __align__(16) bf16 d_Wlo[KTAP * CDIM * CDIM];
__device__ __align__(16) bf16 d_WPh[12 * CDIM * CDIM];     // pointwise weights hi
__device__ __align__(16) bf16 d_WPl[12 * CDIM * CDIM];     // pointwise weights lo
__device__ __align__(16) float d_cntf[NCLS];
__device__ __align__(16) float d_gram[CDIM * CDIM];
__device__ __align__(16) float d_cs[CDIM];
__device__ __align__(16) float d_zstat[3 * 2 * CDIM];
__device__ __align__(16) float d_adp[(size_t)NPTS * 3];
__device__ __align__(16) float d_sb[7][2][CDIM];
__device__ __align__(16) float d_zsb[3][2][CDIM];
__device__ __align__(16) unsigned int d_gmaxu[4];

__device__ __forceinline__ int clpre(int sc) {
    return sc == 0 ? 0 : (sc == 1 ? NCL0 : (NCL0 + NCL1));
}
__device__ __forceinline__ unsigned int fkey(float v) {
    unsigned int b = __float_as_uint(v);
    return (b & 0x80000000u) ? ~b : (b ^ 0x80000000u);
}
__device__ __forceinline__ float funkey(unsigned int u) {
    unsigned int b = (u & 0x80000000u) ? (u ^ 0x80000000u) : ~u;
    return __uint_as_float(b);
}
__device__ __forceinline__ void split1(float v, bf16* H, bf16* L) {
    bf16 h = __float2bfloat16(v);
    *H = h;
    *L = __float2bfloat16(v - __bfloat162float(h));
}
// split 4 consecutive floats -> 8B hi + 8B lo packed stores
__device__ __forceinline__ void split4g(float4 v, bf16* H, bf16* L) {
    bf16 h0, h1, h2, h3, l0, l1, l2, l3;
    split1(v.x, &h0, &l0); split1(v.y, &h1, &l1);
    split1(v.z, &h2, &l2); split1(v.w, &h3, &l3);
    __nv_bfloat162 hp0 = __halves2bfloat162(h0, h1), hp1 = __halves2bfloat162(h2, h3);
    __nv_bfloat162 lp0 = __halves2bfloat162(l0, l1), lp1 = __halves2bfloat162(l2, l3);
    uint2 hu, lu;
    hu.x = *(unsigned int*)&hp0; hu.y = *(unsigned int*)&hp1;
    lu.x = *(unsigned int*)&lp0; lu.y = *(unsigned int*)&lp1;
    *(uint2*)H = hu;
    *(uint2*)L = lu;
}

// ---- wmma building blocks (8 warps, 128x64 @ 64x64, 3-term split) ----
__device__ __forceinline__ void wgemm8(const bf16* Ah, const bf16* Al,
                                       const bf16* Wh, const bf16* Wl,
                                       wmma::fragment<wmma::accumulator, 16, 16, 16, float> cf[4],
                                       int warp) {
#pragma unroll
    for (int s = 0; s < 3; s++) {
        const bf16* Ab = ((s == 1) ? Al : Ah) + warp * 16 * LDH;
        const bf16* Bb = (s == 2) ? Wl : Wh;
#pragma unroll
        for (int kk = 0; kk < 64; kk += 16) {
            wmma::fragment<wmma::matrix_a, 16, 16, 16, bf16, wmma::row_major> af;
            wmma::load_matrix_sync(af, Ab + kk, LDH);
#pragma unroll
            for (int n = 0; n < 4; n++) {
                wmma::fragment<wmma::matrix_b, 16, 16, 16, bf16, wmma::row_major> bf_;
                wmma::load_matrix_sync(bf_, Bb + kk * LDH + n * 16, LDH);
                wmma::mma_sync(cf[n], af, bf_, cf[n]);
            }
        }
    }
}
__device__ __forceinline__ void store_cf(float* Cs,
                                         wmma::fragment<wmma::accumulator, 16, 16, 16, float> cf[4],
                                         int warp) {
#pragma unroll
    for (int n = 0; n < 4; n++)
        wmma::store_matrix_sync(Cs + warp * 16 * LDC + n * 16, cf[n], LDC, wmma::mem_row_major);
}
// load 128-row A tile from global split feat
__device__ __forceinline__ void load_Abf(bf16* Ah, bf16* Al, int base, int tid) {
    int r = tid >> 1, h = (tid & 1) * 32;
    bool v = (base + r) < NPTS;
    const uint4* sh = (const uint4*)(d_Fh + (size_t)(base + r) * 64 + h);
    const uint4* sl = (const uint4*)(d_Fl + (size_t)(base + r) * 64 + h);
    uint4* dh = (uint4*)(Ah + r * LDH + h);
    uint4* dl = (uint4*)(Al + r * LDH + h);
    uint4 z = {0, 0, 0, 0};
#pragma unroll
    for (int i = 0; i < 4; i++) { dh[i] = v ? sh[i] : z; dl[i] = v ? sl[i] : z; }
}
// load 64x64 W tile from split weight slot
__device__ __forceinline__ void load_Wbf(bf16* Wh, bf16* Wl, int slot, int tid) {
    const uint4* gh = (const uint4*)(d_WPh + (size_t)slot * 4096);
    const uint4* gl = (const uint4*)(d_WPl + (size_t)slot * 4096);
#pragma unroll
    for (int i = 0; i < 2; i++) {
        int flat8 = (tid + i * 256) * 8;
        int row = flat8 >> 6, col = flat8 & 63;
        *(uint4*)(Wh + row * LDH + col) = gh[tid + i * 256];
        *(uint4*)(Wl + row * LDH + col) = gl[tid + i * 256];
    }
}

// SIMT gemm (kept for k_Mw only)
__device__ __forceinline__ void gemm64(const float* __restrict__ Xs,
                                       const float* __restrict__ Ws,
                                       float acc[4][8], int r0, int c0) {
#pragma unroll
    for (int cc = 0; cc < 64; cc += 4) {
        float4 a4[4];
#pragma unroll
        for (int r = 0; r < 4; r++) a4[r] = *(const float4*)(Xs + (r0 + r) * 64 + cc);
#pragma unroll
        for (int u = 0; u < 4; u++) {
            float4 w0 = *(const float4*)(Ws + (cc + u) * 64 + c0);
            float4 w1 = *(const float4*)(Ws + (cc + u) * 64 + c0 + 4);
#pragma unroll
            for (int r = 0; r < 4; r++) {
                float a = (u == 0) ? a4[r].x : (u == 1) ? a4[r].y : (u == 2) ? a4[r].z : a4[r].w;
                acc[r][0] += a * w0.x; acc[r][1] += a * w0.y;
                acc[r][2] += a * w0.z; acc[r][3] += a * w0.w;
                acc[r][4] += a * w1.x; acc[r][5] += a * w1.y;
                acc[r][6] += a * w1.z; acc[r][7] += a * w1.w;
            }
        }
    }
}
__device__ __forceinline__ void load_W(float* Ws, const float* __restrict__ src, int tid) {
    const float4* s = (const float4*)src;
    float4* d = (float4*)Ws;
#pragma unroll
    for (int i = 0; i < 4; i++) d[tid + i * 256] = s[tid + i * 256];
}
__device__ __forceinline__ void stat_reduce(float* scratch, const float csum[8],
                                            const float csq[8], int tid, int c0,
                                            int statq) {
    int rg = tid >> 3;
#pragma unroll
    for (int j = 0; j < 8; j++) {
        scratch[rg * 64 + c0 + j] = csum[j];
        scratch[2048 + rg * 64 + c0 + j] = csq[j];
    }
    __syncthreads();
    if (tid < 128) {
        int part = tid >> 6;
        int c = tid & 63;
        const float* p = scratch + part * 2048 + c;
        float tot = 0.f;
#pragma unroll
        for (int rg2 = 0; rg2 < 32; rg2++) tot += p[rg2 * 64];
        atomicAdd(&d_zstat[statq * 128 + part * 64 + c], tot);
    }
}

// ---------------------------------------------------------------------------
__global__ __launch_bounds__(256) void k_zero() {
    long long i = (long long)blockIdx.x * 256 + threadIdx.x;
    long long stride = (long long)gridDim.x * 256;
    const long long nS = (long long)NCLS * CDIM;
    for (long long idx = i; idx < nS; idx += stride) {
        d_S[idx] = 0.f; d_D[idx] = 0.f; d_G[idx] = 0.f;
    }
    for (long long idx = i; idx < NCLS; idx += stride) d_cntf[idx] = 0.f;
    if (i < 4096) d_gram[i] = 0.f;
    if (i < 64) d_cs[i] = 0.f;
    if (i < 384) d_zstat[i] = 0.f;
    if (i < 3) d_gmaxu[i] = 0x007FFFFFu;
}

// Gram + column sums + counts + adp softmax + feat hi/lo split
__global__ __launch_bounds__(256) void k_gram(const float* __restrict__ feat,
                                              const int* __restrict__ cl0,
                                              const int* __restrict__ cl1,
                                              const int* __restrict__ cl2,
                                              const float* __restrict__ W_adp) {
    __shared__ __align__(16) float Xs[128 * 64];
    __shared__ float Was[CDIM * 3];
    int tid = threadIdx.x;
    int base = blockIdx.x * 128;
    {
        int r = tid >> 1, h = (tid & 1) * 32;
        bool v = (base + r) < NPTS;
        const float4* s = (const float4*)(feat + (size_t)(base + r) * 64 + h);
        float4* d = (float4*)(Xs + r * 64 + h);
        float4 z = make_float4(0.f, 0.f, 0.f, 0.f);
#pragma unroll
        for (int i = 0; i < 8; i++) {
            float4 x = v ? s[i] : z;
            d[i] = x;
            if (v) {
                size_t p = (size_t)(base + r) * 64 + h + i * 4;
                split4g(x, d_Fh + p, d_Fl + p);
            }
        }
    }
    if (tid < CDIM * 3) Was[tid] = W_adp[tid];
    __syncthreads();

    if (tid < 128 && base + tid < NPTS) {
        int n = base + tid;
        atomicAdd(&d_cntf[cl0[n]], 1.f);
        atomicAdd(&d_cntf[NCL0 + cl1[n]], 1.f);
        atomicAdd(&d_cntf[NCL0 + NCL1 + cl2[n]], 1.f);
        float a0 = 0.f, a1 = 0.f, a2 = 0.f;
#pragma unroll 8
        for (int c = 0; c < 64; c++) {
            float x = Xs[tid * 64 + c];
            a0 += x * Was[c * 3 + 0];
            a1 += x * Was[c * 3 + 1];
            a2 += x * Was[c * 3 + 2];
        }
        float mx = fmaxf(a0, fmaxf(a1, a2));
        float e0 = expf(a0 - mx), e1 = expf(a1 - mx), e2 = expf(a2 - mx);
        float inv = 1.f / (e0 + e1 + e2);
        d_adp[(size_t)n * 3 + 0] = e0 * inv;
        d_adp[(size_t)n * 3 + 1] = e1 * inv;
        d_adp[(size_t)n * 3 + 2] = e2 * inv;
    }

    int i = tid & 63;
    int j0 = (tid >> 6) * 16;
    float acc[16];
#pragma unroll
    for (int q = 0; q < 16; q++) acc[q] = 0.f;
    for (int m = 0; m < 128; m++) {
        float a = Xs[m * 64 + i];
        const float4* xr = (const float4*)(Xs + m * 64 + j0);
#pragma unroll
        for (int q = 0; q < 4; q++) {
            float4 w = xr[q];
            acc[q * 4 + 0] += a * w.x; acc[q * 4 + 1] += a * w.y;
            acc[q * 4 + 2] += a * w.z; acc[q * 4 + 3] += a * w.w;
        }
    }
#pragma unroll
    for (int q = 0; q < 16; q++)
        atomicAdd(&d_gram[i * 64 + j0 + q], acc[q]);

    if (tid < 64) {
        float s = 0.f;
        for (int m = 0; m < 128; m++) s += Xs[m * 64 + tid];
        atomicAdd(&d_cs[tid], s);
    }
}

__global__ __launch_bounds__(512) void k_fold(const float* __restrict__ W_lw,
                                              const float* __restrict__ g_lw,
                                              const float* __restrict__ b_lw,
                                              const float* __restrict__ W_proj,
                                              const float* __restrict__ g_proj,
                                              const float* __restrict__ b_proj) {
    __shared__ __align__(16) float Gs[64 * 64];
    __shared__ float cs[64];
    int tid = threadIdx.x;
    for (int idx = tid; idx < 4096; idx += blockDim.x) Gs[idx] = d_gram[idx];
    if (tid < 64) cs[tid] = d_cs[tid];
    __syncthreads();
    if (tid < 448) {
        int q = tid >> 6, j = tid & 63;
        const float* W = q < 3 ? W_lw + q * 4096 : W_proj + (q - 3) * 4096;
        const float* g = q < 3 ? g_lw + q * 64 : g_proj + (q - 3) * 64;
        const float* b = q < 3 ? b_lw + q * 64 : b_proj + (q - 3) * 64;
        float wcol[64];
        for (int i = 0; i < 64; i++) wcol[i] = W[i * 64 + j];
        float mean = 0.f, m2 = 0.f;
        for (int i = 0; i < 64; i++) {
            mean += cs[i] * wcol[i];
            float t = 0.f;
            for (int i2 = 0; i2 < 64; i2++) t += Gs[i * 64 + i2] * wcol[i2];
            m2 += wcol[i] * t;
        }
        float invN = 1.f / (float)NPTS;
        mean *= invN; m2 *= invN;
        float var = m2 - mean * mean;
        float s = g[j] * rsqrtf(var + 1e-3f);
        d_sb[q][0][j] = s;
        d_sb[q][1][j] = b[j] - mean * s;
    }
}

// split 12 pointwise weight matrices: [lw0..2 | w0..2 | proj0..3 | fuse0..1]
__global__ __launch_bounds__(256) void k_cvtWp(const float* __restrict__ W_lw,
                                               const float* __restrict__ W_w,
                                               const float* __restrict__ W_proj,
                                               const float* __restrict__ W_fuse) {
    int i = blockIdx.x * 256 + threadIdx.x;
    if (i >= 12 * 4096) return;
    int slot = i >> 12, off = i & 4095;
    float v;
    if (slot < 3)       v = W_lw[slot * 4096 + off];
    else if (slot < 6)  v = W_w[(slot - 3) * 4096 + off];
    else if (slot < 10) v = W_proj[(slot - 6) * 4096 + off];
    else                v = W_fuse[(slot - 10) * 4096 + off];
    split1(v, d_WPh + i, d_WPl + i);
}

// P = relu(bn(feat@W_lw)) [smem]; S[cl]+=P; U = P@W_w -> B2.  (tensor cores)
__global__ __launch_bounds__(256) void k_PUw(const int* __restrict__ cl, int sc) {
    extern __shared__ __align__(16) char sm[];
    bf16* Ah = (bf16*)sm;
    bf16* Al = Ah + 128 * LDH;
    char* r2 = sm + (size_t)2 * 128 * LDH * 2;
    bf16* Wh = (bf16*)r2;
    bf16* Wl = Wh + 64 * LDH;
    float* Cs = (float*)r2;
    int tid = threadIdx.x, base = blockIdx.x * 128, warp = tid >> 5;
    int r0 = (tid >> 3) * 4, c0 = (tid & 7) * 8;

    load_Abf(Ah, Al, base, tid);
    load_Wbf(Wh, Wl, sc, tid);
    __syncthreads();
    wmma::fragment<wmma::accumulator, 16, 16, 16, float> cf[4];
#pragma unroll
    for (int n = 0; n < 4; n++) wmma::fill_fragment(cf[n], 0.f);
    wgemm8(Ah, Al, Wh, Wl, cf, warp);
    __syncthreads();
    store_cf(Cs, cf, warp);
    __syncthreads();

    float* S = d_S + (size_t)clpre(sc) * CDIM;
    float y[4][8];
#pragma unroll
    for (int j = 0; j < 8; j++) {
        float s = d_sb[sc][0][c0 + j], b = d_sb[sc][1][c0 + j];
#pragma unroll
        for (int r = 0; r < 4; r++)
            y[r][j] = fmaxf(Cs[(r0 + r) * LDC + c0 + j] * s + b, 0.f);
    }
#pragma unroll
    for (int r = 0; r < 4; r++) {
        int m = base + r0 + r;
        if (m < NPTS) {
            size_t cb = (size_t)cl[m] * 64;
#pragma unroll
            for (int j = 0; j < 8; j++) atomicAdd(&S[cb + c0 + j], y[r][j]);
        }
    }
    // split P into A tiles (feat tiles no longer needed)
#pragma unroll
    for (int r = 0; r < 4; r++)
#pragma unroll
        for (int j = 0; j < 8; j++)
            split1(y[r][j], &Ah[(r0 + r) * LDH + c0 + j], &Al[(r0 + r) * LDH + c0 + j]);
    __syncthreads();                    // all Cs reads done -> reuse as W
    load_Wbf(Wh, Wl, 3 + sc, tid);
    __syncthreads();
#pragma unroll
    for (int n = 0; n < 4; n++) wmma::fill_fragment(cf[n], 0.f);
    wgemm8(Ah, Al, Wh, Wl, cf, warp);
    __syncthreads();
    store_cf(Cs, cf, warp);
    __syncthreads();
#pragma unroll
    for (int r = 0; r < 4; r++) {
        int m = base + r0 + r;
        if (m < NPTS) {
            float4 v0 = *(float4*)(Cs + (r0 + r) * LDC + c0);
            float4 v1 = *(float4*)(Cs + (r0 + r) * LDC + c0 + 4);
            *(float4*)(d_B2 + (size_t)m * 64 + c0) = v0;
            *(float4*)(d_B2 + (size_t)m * 64 + c0 + 4) = v1;
        }
    }
}

// Mw[c] = (S[c]/max(cnt,1)) @ W_w  (SIMT; tiny)
__global__ __launch_bounds__(256) void k_Mw(const float* __restrict__ Ww, int sc, int ncl) {
    __shared__ __align__(16) float Xs[128 * 64];
    __shared__ __align__(16) float Ws[64 * 64];
    int tid = threadIdx.x, base = blockIdx.x * 128;
    const float* S = d_S + (size_t)clpre(sc) * CDIM;
    const float* cnt = d_cntf + clpre(sc);
    {
        int r = tid >> 1, h = (tid & 1) * 32;
        int cr = base + r;
        bool v = cr < ncl;
        float inv = 0.f;
        if (v) inv = 1.f / fmaxf(cnt[cr], 1.f);
        const float4* s4 = (const float4*)(S + (size_t)cr * 64 + h);
        float4* dd = (float4*)(Xs + r * 64 + h);
        float4 z = make_float4(0.f, 0.f, 0.f, 0.f);
#pragma unroll
        for (int i = 0; i < 8; i++) {
            float4 x = v ? s4[i] : z;
            x.x *= inv; x.y *= inv; x.z *= inv; x.w *= inv;
            dd[i] = x;
        }
    }
    load_W(Ws, Ww, tid);
    __syncthreads();
    int r0 = (tid >> 3) * 4, c0 = (tid & 7) * 8;
    float acc[4][8] = {};
    gemm64(Xs, Ws, acc, r0, c0);
#pragma unroll
    for (int r = 0; r < 4; r++) {
        int m = base + r0 + r;
        if (m < ncl)
#pragma unroll
            for (int j = 0; j < 8; j++) d_Mw[(size_t)m * 64 + c0 + j] = acc[r][j];
    }
}

// T = U - Mw[cl]; global max
__global__ __launch_bounds__(256) void k_maxU(const int* __restrict__ cl, int sc) {
    long long i = (long long)blockIdx.x * 256 + threadIdx.x;
    float lmax = -3.402823466e38f;
    if (i < E4) {
        long long row = i >> 4;
        int c4 = (int)(i & 15) * 4;
        float4 u = *(float4*)(d_B2 + row * 64 + c4);
        size_t cb = (size_t)cl[row] * 64 + c4;
        float4 m = *(const float4*)(d_Mw + cb);
        float4 t;
        t.x = u.x - m.x; t.y = u.y - m.y; t.z = u.z - m.z; t.w = u.w - m.w;
        *(float4*)(d_B2 + row * 64 + c4) = t;
        lmax = fmaxf(fmaxf(t.x, t.y), fmaxf(t.z, t.w));
    }
#pragma unroll
    for (int off = 16; off > 0; off >>= 1)
        lmax = fmaxf(lmax, __shfl_xor_sync(0xFFFFFFFFu, lmax, off));
    if ((threadIdx.x & 31) == 0) atomicMax(&d_gmaxu[sc], fkey(lmax));
}

// E = exp(T - max); D[cl] += E
__global__ __launch_bounds__(256) void k_E(const int* __restrict__ cl, int sc) {
    long long i = (long long)blockIdx.x * 256 + threadIdx.x;
    if (i >= E4) return;
    long long row = i >> 4;
    int c4 = (int)(i & 15) * 4;
    float M = funkey(d_gmaxu[sc]);
    float* D = d_D + (size_t)clpre(sc) * CDIM;
    float4 t = *(float4*)(d_B2 + row * 64 + c4);
    float4 e;
    e.x = expf(t.x - M); e.y = expf(t.y - M);
    e.z = expf(t.z - M); e.w = expf(t.w - M);
    *(float4*)(d_B2 + row * 64 + c4) = e;
    size_t cb = (size_t)cl[row] * 64 + c4;
    atomicAdd(&D[cb + 0], e.x); atomicAdd(&D[cb + 1], e.y);
    atomicAdd(&D[cb + 2], e.z); atomicAdd(&D[cb + 3], e.w);
}

// F = relu(bn(feat@W_proj)); G[cl] += F*E/(D[cl]+1e-6)  (tensor cores)
__global__ __launch_bounds__(256) void k_Fw(const int* __restrict__ cl, int sc) {
    extern __shared__ __align__(16) char sm[];
    bf16* Ah = (bf16*)sm;
    bf16* Al = Ah + 128 * LDH;
    char* r2 = sm + (size_t)2 * 128 * LDH * 2;
    bf16* Wh = (bf16*)r2;
    bf16* Wl = Wh + 64 * LDH;
    float* Cs = (float*)r2;
    int tid = threadIdx.x, base = blockIdx.x * 128, warp = tid >> 5;
    int r0 = (tid >> 3) * 4, c0 = (tid & 7) * 8;

    load_Abf(Ah, Al, base, tid);
    load_Wbf(Wh, Wl, 6 + sc, tid);
    __syncthreads();
    wmma::fragment<wmma::accumulator, 16, 16, 16, float> cf[4];
#pragma unroll
    for (int n = 0; n < 4; n++) wmma::fill_fragment(cf[n], 0.f);
    wgemm8(Ah, Al, Wh, Wl, cf, warp);
    __syncthreads();
    store_cf(Cs, cf, warp);
    __syncthreads();

    int sb = 3 + sc;
    float* D = d_D + (size_t)clpre(sc) * CDIM;
    float* G = d_G + (size_t)clpre(sc) * CDIM;
    float s[8], b[8];
#pragma unroll
    for (int j = 0; j < 8; j++) { s[j] = d_sb[sb][0][c0 + j]; b[j] = d_sb[sb][1][c0 + j]; }
#pragma unroll
    for (int r = 0; r < 4; r++) {
        int m = base + r0 + r;
        if (m < NPTS) {
            size_t cb = (size_t)cl[m] * 64;
#pragma unroll
            for (int j = 0; j < 8; j++) {
                float F = fmaxf(Cs[(r0 + r) * LDC + c0 + j] * s[j] + b[j], 0.f);
                float e = d_B2[(size_t)m * 64 + c0 + j];
                float dn = D[cb + c0 + j] + 1e-6f;
                atomicAdd(&G[cb + c0 + j], F * e / dn);
            }
        }
    }
}

// z = [f_last, mix] @ W_fuse -> B1 + fuse BN stats  (tensor cores)
__global__ __launch_bounds__(256) void k_fusew(const int* __restrict__ cl0,
                                               const int* __restrict__ cl1,
                                               const int* __restrict__ cl2) {
    extern __shared__ __align__(16) char sm[];
    bf16* Ah = (bf16*)sm;
    bf16* Al = Ah + 128 * LDH;
    char* r2 = sm + (size_t)2 * 128 * LDH * 2;
    bf16* Wh = (bf16*)r2;
    bf16* Wl = Wh + 64 * LDH;
    float* Cs = (float*)r2;
    float* scratch = (float*)(r2 + 128 * LDC * 4);
    int tid = threadIdx.x, base = blockIdx.x * 128, warp = tid >> 5;
    int r0 = (tid >> 3) * 4, c0 = (tid & 7) * 8;

    // stage 1: f_last = relu(bn(feat @ proj3))
    load_Abf(Ah, Al, base, tid);
    load_Wbf(Wh, Wl, 9, tid);
    __syncthreads();
    wmma::fragment<wmma::accumulator, 16, 16, 16, float> cf[4];
#pragma unroll
    for (int n = 0; n < 4; n++) wmma::fill_fragment(cf[n], 0.f);
    wgemm8(Ah, Al, Wh, Wl, cf, warp);
    __syncthreads();
    store_cf(Cs, cf, warp);
    __syncthreads();
#pragma unroll
    for (int j = 0; j < 8; j++) {
        float s = d_sb[6][0][c0 + j], b = d_sb[6][1][c0 + j];
#pragma unroll
        for (int r = 0; r < 4; r++) {
            float fl = fmaxf(Cs[(r0 + r) * LDC + c0 + j] * s + b, 0.f);
            split1(fl, &Ah[(r0 + r) * LDH + c0 + j], &Al[(r0 + r) * LDH + c0 + j]);
        }
    }
    __syncthreads();                    // Cs reads done -> reuse as W
    // stage 2: z = f_last @ fuse0
    load_Wbf(Wh, Wl, 10, tid);
    __syncthreads();
    wmma::fragment<wmma::accumulator, 16, 16, 16, float> cz[4];
#pragma unroll
    for (int n = 0; n < 4; n++) wmma::fill_fragment(cz[n], 0.f);
    wgemm8(Ah, Al, Wh, Wl, cz, warp);
    __syncthreads();                    // A reads done -> overwrite with mix
    // stage 3: mix gather + z += mix @ fuse1
    const float* G0 = d_G;
    const float* G1 = d_G + (size_t)NCL0 * CDIM;
    const float* G2 = d_G + (size_t)(NCL0 + NCL1) * CDIM;
#pragma unroll
    for (int r = 0; r < 4; r++) {
        int m = base + r0 + r;
        if (m < NPTS) {
            float a0 = d_adp[(size_t)m * 3 + 0];
            float a1 = d_adp[(size_t)m * 3 + 1];
            float a2 = d_adp[(size_t)m * 3 + 2];
            size_t cb0 = (size_t)cl0[m] * 64, cb1 = (size_t)cl1[m] * 64, cb2 = (size_t)cl2[m] * 64;
#pragma unroll
            for (int j = 0; j < 8; j++) {
                int c = c0 + j;
                float mix = a0 * G0[cb0 + c] + a1 * G1[cb1 + c] + a2 * G2[cb2 + c];
                split1(mix, &Ah[(r0 + r) * LDH + c], &Al[(r0 + r) * LDH + c]);
            }
        } else {
#pragma unroll
            for (int j = 0; j < 8; j++) {
                Ah[(r0 + r) * LDH + c0 + j] = __float2bfloat16(0.f);
                Al[(r0 + r) * LDH + c0 + j] = __float2bfloat16(0.f);
            }
        }
    }
    load_Wbf(Wh, Wl, 11, tid);
    __syncthreads();
    wgemm8(Ah, Al, Wh, Wl, cz, warp);
    __syncthreads();
    store_cf(Cs, cz, warp);
    __syncthreads();

    float csum[8] = {}, csq[8] = {};
#pragma unroll
    for (int r = 0; r < 4; r++) {
        int m = base + r0 + r;
        if (m < NPTS) {
            float4 v0 = *(float4*)(Cs + (r0 + r) * LDC + c0);
            float4 v1 = *(float4*)(Cs + (r0 + r) * LDC + c0 + 4);
            *(float4*)(d_B1 + (size_t)m * 64 + c0) = v0;
            *(float4*)(d_B1 + (size_t)m * 64 + c0 + 4) = v1;
            csum[0] += v0.x; csq[0] += v0.x * v0.x;
            csum[1] += v0.y; csq[1] += v0.y * v0.y;
            csum[2] += v0.z; csq[2] += v0.z * v0.z;
            csum[3] += v0.w; csq[3] += v0.w * v0.w;
            csum[4] += v1.x; csq[4] += v1.x * v1.x;
            csum[5] += v1.y; csq[5] += v1.y * v1.y;
            csum[6] += v1.z; csq[6] += v1.z * v1.z;
            csum[7] += v1.w; csq[7] += v1.w * v1.w;
        }
    }
    stat_reduce(scratch, csum, csq, tid, c0, 0);
}

__global__ void k_bnstat(const float* __restrict__ g, const float* __restrict__ b, int q) {
    int c = threadIdx.x;
    if (c < 64) {
        float sum = d_zstat[q * 128 + c];
        float sq = d_zstat[q * 128 + 64 + c];
        float invN = 1.f / (float)NPTS;
        float mean = sum * invN;
        float var = sq * invN - mean * mean;
        float s = g[c] * rsqrtf(var + 1e-3f);
        d_zsb[q][0][c] = s;
        d_zsb[q][1][c] = b[c] - mean * s;
    }
}

// fused = relu(bn(z)) + feat -> B2 + hi/lo split
__global__ __launch_bounds__(256) void k_applyfuse(const float* __restrict__ feat) {
    long long i = (long long)blockIdx.x * 256 + threadIdx.x;
    if (i >= E4) return;
    long long row = i >> 4;
    int c4 = (int)(i & 15) * 4;
    float4 zv = *(float4*)(d_B1 + row * 64 + c4);
    float4 fv = *(const float4*)(feat + row * 64 + c4);
    float4 o;
    o.x = fmaxf(zv.x * d_zsb[0][0][c4 + 0] + d_zsb[0][1][c4 + 0], 0.f) + fv.x;
    o.y = fmaxf(zv.y * d_zsb[0][0][c4 + 1] + d_zsb[0][1][c4 + 1], 0.f) + fv.y;
    o.z = fmaxf(zv.z * d_zsb[0][0][c4 + 2] + d_zsb[0][1][c4 + 2], 0.f) + fv.z;
    o.w = fmaxf(zv.w * d_zsb[0][0][c4 + 3] + d_zsb[0][1][c4 + 3], 0.f) + fv.w;
    size_t p = row * 64 + c4;
    *(float4*)(d_B2 + p) = o;
    split4g(o, d_Hc + p, d_Lc + p);
}

// B1 = relu(bn(B1)) + hi/lo split
__global__ __launch_bounds__(256) void k_apply1() {
    long long i = (long long)blockIdx.x * 256 + threadIdx.x;
    if (i >= E4) return;
    long long row = i >> 4;
    int c4 = (int)(i & 15) * 4;
    float4 h = *(float4*)(d_B1 + row * 64 + c4);
    h.x = fmaxf(h.x * d_zsb[1][0][c4 + 0] + d_zsb[1][1][c4 + 0], 0.f);
    h.y = fmaxf(h.y * d_zsb[1][0][c4 + 1] + d_zsb[1][1][c4 + 1], 0.f);
    h.z = fmaxf(h.z * d_zsb[1][0][c4 + 2] + d_zsb[1][1][c4 + 2], 0.f);
    h.w = fmaxf(h.w * d_zsb[1][0][c4 + 3] + d_zsb[1][1][c4 + 3], 0.f);
    size_t p = row * 64 + c4;
    *(float4*)(d_B1 + p) = h;
    split4g(h, d_Hc + p, d_Lc + p);
}

__global__ __launch_bounds__(256) void k_cvtW(const float* __restrict__ W) {
    int i = blockIdx.x * 256 + threadIdx.x;
    if (i < KTAP * 4096) split1(W[i], d_Whi + i, d_Wlo + i);
}

// submanifold conv, bf16-split wmma
__global__ __launch_bounds__(256) void k_convw(const int* __restrict__ nbr,
                                               int mode, int statq) {
    extern __shared__ __align__(16) char smraw[];
    bf16* Ah = (bf16*)smraw;
    bf16* Al = Ah + 128 * LDH;
    bf16* Wh = Al + 128 * LDH;
    bf16* Wl = Wh + 64 * LDH;
    float* Cs = (float*)smraw;

    int tid = threadIdx.x, base = blockIdx.x * 128;
    int warp = tid >> 5;
    int gr = tid >> 1, gh = (tid & 1) * 32;
    bool gv = (base + gr) < NPTS;

    uint4 pah[4], pal[4], pwh[2], pwl[2];
    auto prefA = [&](int k) {
        int j = gv ? nbr[(size_t)(base + gr) * KTAP + k] : 0;
        const uint4* sh = (const uint4*)(d_Hc + (size_t)j * 64 + gh);
        const uint4* sl = (const uint4*)(d_Lc + (size_t)j * 64 + gh);
#pragma unroll
        for (int i = 0; i < 4; i++) { pah[i] = sh[i]; pal[i] = sl[i]; }
    };
    auto prefW = [&](int k) {
        const uint4* swh = (const uint4*)(d_Whi + (size_t)k * 4096);
        const uint4* swl = (const uint4*)(d_Wlo + (size_t)k * 4096);
#pragma unroll
        for (int i = 0; i < 2; i++) { pwh[i] = swh[tid + i * 256]; pwl[i] = swl[tid + i * 256]; }
    };

    wmma::fragment<wmma::accumulator, 16, 16, 16, float> cf[4];
#pragma unroll
    for (int n = 0; n < 4; n++) wmma::fill_fragment(cf[n], 0.f);

    prefA(0); prefW(0);
    for (int k = 0; k < KTAP; k++) {
        __syncthreads();
        {
            uint4* dh = (uint4*)(Ah + gr * LDH + gh);
            uint4* dl = (uint4*)(Al + gr * LDH + gh);
#pragma unroll
            for (int i = 0; i < 4; i++) { dh[i] = pah[i]; dl[i] = pal[i]; }
#pragma unroll
            for (int i = 0; i < 2; i++) {
                int flat8 = (tid + i * 256) * 8;
                int row = flat8 >> 6, col = flat8 & 63;
                *(uint4*)(Wh + row * LDH + col) = pwh[i];
                *(uint4*)(Wl + row * LDH + col) = pwl[i];
            }
        }
        __syncthreads();
        if (k + 1 < KTAP) { prefA(k + 1); prefW(k + 1); }
        wgemm8(Ah, Al, Wh, Wl, cf, warp);
    }
    __syncthreads();
    store_cf(Cs, cf, warp);
    __syncthreads();

    float* fout = (mode == 0) ? d_B1 : d_B3;
    int r0 = (tid >> 3) * 4, c0 = (tid & 7) * 8;
    float csum[8] = {}, csq[8] = {};
#pragma unroll
    for (int r = 0; r < 4; r++) {
        int m = base + r0 + r;
        if (m < NPTS) {
            float4 v0 = *(float4*)(Cs + (r0 + r) * LDC + c0);
            float4 v1 = *(float4*)(Cs + (r0 + r) * LDC + c0 + 4);
            *(float4*)(fout + (size_t)m * 64 + c0) = v0;
            *(float4*)(fout + (size_t)m * 64 + c0 + 4) = v1;
            csum[0] += v0.x; csq[0] += v0.x * v0.x;
            csum[1] += v0.y; csq[1] += v0.y * v0.y;
            csum[2] += v0.z; csq[2] += v0.z * v0.z;
            csum[3] += v0.w; csq[3] += v0.w * v0.w;
            csum[4] += v1.x; csq[4] += v1.x * v1.x;
            csum[5] += v1.y; csq[5] += v1.y * v1.y;
            csum[6] += v1.z; csq[6] += v1.z * v1.z;
            csum[7] += v1.w; csq[7] += v1.w * v1.w;
        }
    }
    stat_reduce(Cs + 128 * LDC, csum, csq, tid, c0, statq);
}

__global__ __launch_bounds__(256) void k_final(float* __restrict__ out) {
    long long i = (long long)blockIdx.x * 256 + threadIdx.x;
    if (i >= E4) return;
    long long row = i >> 4;
    int c4 = (int)(i & 15) * 4;
    float4 h = *(float4*)(d_B3 + row * 64 + c4);
    float4 r = *(float4*)(d_B2 + row * 64 + c4);
    float4 o;
    o.x = fmaxf(h.x * d_zsb[2][0][c4 + 0] + d_zsb[2][1][c4 + 0] + r.x, 0.f);
    o.y = fmaxf(h.y * d_zsb[2][0][c4 + 1] + d_zsb[2][1][c4 + 1] + r.y, 0.f);
    o.z = fmaxf(h.z * d_zsb[2][0][c4 + 2] + d_zsb[2][1][c4 + 2] + r.z, 0.f);
    o.w = fmaxf(h.w * d_zsb[2][0][c4 + 3] + d_zsb[2][1][c4 + 3] + r.w, 0.f);
    *(float4*)(out + row * 64 + c4) = o;
}

// ---------------------------------------------------------------------------
extern "C" void kernel_launch(void* const* d_in, const int* in_sizes, int n_in,
                              void* d_out, int out_size) {
    (void)in_sizes; (void)n_in; (void)out_size;
    const float* feat   = (const float*)d_in[0];
    const int*   cl0    = (const int*)d_in[1];
    const int*   cl1    = (const int*)d_in[2];
    const int*   cl2    = (const int*)d_in[3];
    const int*   nbr    = (const int*)d_in[4];
    const float* W_lw   = (const float*)d_in[5];
    const float* g_lw   = (const float*)d_in[6];
    const float* b_lw   = (const float*)d_in[7];
    const float* W_w    = (const float*)d_in[8];
    const float* W_proj = (const float*)d_in[9];
    const float* g_proj = (const float*)d_in[10];
    const float* b_proj = (const float*)d_in[11];
    const float* W_adp  = (const float*)d_in[12];
    const float* W_fuse = (const float*)d_in[13];
    const float* g_fuse = (const float*)d_in[14];
    const float* b_fuse = (const float*)d_in[15];
    const float* W_c1   = (const float*)d_in[16];
    const float* g_c1   = (const float*)d_in[17];
    const float* b_c1   = (const float*)d_in[18];
    const float* W_c2   = (const float*)d_in[19];
    const float* g_c2   = (const float*)d_in[20];
    const float* b_c2   = (const float*)d_in[21];
    float* out = (float*)d_out;

    cudaFuncSetAttribute(k_convw, cudaFuncAttributeMaxDynamicSharedMemorySize, SMEMW);
    cudaFuncSetAttribute(k_PUw,   cudaFuncAttributeMaxDynamicSharedMemorySize, SMEMP);
    cudaFuncSetAttribute(k_Fw,    cudaFuncAttributeMaxDynamicSharedMemorySize, SMEMP);
    cudaFuncSetAttribute(k_fusew, cudaFuncAttributeMaxDynamicSharedMemorySize, SMEMP);

    const int ncl[3] = {NCL0, NCL1, NCL2};
    const int* cls[3] = {cl0, cl1, cl2};
    const int e4grid = (E4 + 255) / 256;

    k_zero<<<2048, 256>>>();
    k_gram<<<NT, 256>>>(feat, cl0, cl1, cl2, W_adp);
    k_fold<<<1, 512>>>(W_lw, g_lw, b_lw, W_proj, g_proj, b_proj);
    k_cvtWp<<<(12 * 4096 + 255) / 256, 256>>>(W_lw, W_w, W_proj, W_fuse);

    for (int sc = 0; sc < 3; sc++) {
        k_PUw<<<NT, 256, SMEMP>>>(cls[sc], sc);
        k_Mw<<<(ncl[sc] + 127) / 128, 256>>>(W_w + sc * 4096, sc, ncl[sc]);
        k_maxU<<<e4grid, 256>>>(cls[sc], sc);
        k_E<<<e4grid, 256>>>(cls[sc], sc);
        k_Fw<<<NT, 256, SMEMP>>>(cls[sc], sc);
    }

    k_fusew<<<NT, 256, SMEMP>>>(cl0, cl1, cl2);
    k_bnstat<<<1, 64>>>(g_fuse, b_fuse, 0);
    k_applyfuse<<<e4grid, 256>>>(feat);

    k_cvtW<<<(KTAP * 4096 + 255) / 256, 256>>>(W_c1);
    k_convw<<<NT, 256, SMEMW>>>(nbr, 0, 1);
    k_bnstat<<<1, 64>>>(g_c1, b_c1, 1);
    k_apply1<<<e4grid, 256>>>();

    k_cvtW<<<(KTAP * 4096 + 255) / 256, 256>>>(W_c2);
    k_convw<<<NT, 256, SMEMW>>>(nbr, 1, 2);
    k_bnstat<<<1, 64>>>(g_c2, b_c2, 2);
    k_final<<<e4grid, 256>>>(out);
}